// round 12
// baseline (speedup 1.0000x reference)
#include <cuda_runtime.h>
#include <math.h>

#define BATCH 64
#define WLEN  160000
#define NFRM  313          // 1 + 160000/512
#define HOP   512
#define NFFT  2048
#define MHALF 1024         // complex FFT length
#define NMELS 128
#define NPTS  130          // mel breakpoints

#define SK2(i) ((i) + ((i) >> 4))    // skew (slots are float4)
#define ZLEN4  1092

#define NCHUNK 8
#define CHLEN  40                    // 7*40 + 33 = 313

typedef unsigned long long ull;

__device__ float g_mel[BATCH * NFRM * NMELS];    // mel power, layout [b][t][m]
__device__ float g_part[BATCH * NCHUNK * NMELS]; // per-chunk partial IIR sums

// ---------------- packed f32x2 helpers ----------------
__device__ __forceinline__ ull pk2(float lo, float hi) {
    ull r; asm("mov.b64 %0, {%1, %2};" : "=l"(r) : "f"(lo), "f"(hi)); return r;
}
__device__ __forceinline__ ull bc2(float v) { return pk2(v, v); }
__device__ __forceinline__ void upk2(float& lo, float& hi, ull v) {
    asm("mov.b64 {%0, %1}, %2;" : "=f"(lo), "=f"(hi) : "l"(v));
}
__device__ __forceinline__ ull add2(ull a, ull b) {
    ull r; asm("add.rn.f32x2 %0, %1, %2;" : "=l"(r) : "l"(a), "l"(b)); return r;
}
__device__ __forceinline__ ull sub2(ull a, ull b) {
    ull r; asm("sub.rn.f32x2 %0, %1, %2;" : "=l"(r) : "l"(a), "l"(b)); return r;
}
__device__ __forceinline__ ull mul2(ull a, ull b) {
    ull r; asm("mul.rn.f32x2 %0, %1, %2;" : "=l"(r) : "l"(a), "l"(b)); return r;
}
__device__ __forceinline__ ull fma2(ull a, ull b, ull c) {
    ull r; asm("fma.rn.f32x2 %0, %1, %2, %3;" : "=l"(r) : "l"(a), "l"(b), "l"(c)); return r;
}

struct c2  { ull re, im; };                 // complex, 2 frames packed per component
struct tw2 { ull r, i, in; };               // packed twiddle

__device__ __forceinline__ float2 cmul(float2 a, float2 b) {
    return make_float2(a.x * b.x - a.y * b.y, a.x * b.y + a.y * b.x);
}
__device__ __forceinline__ tw2 mktw(float2 w) {
    tw2 t; t.r = bc2(w.x); t.i = bc2(w.y); t.in = bc2(-w.y); return t;
}
__device__ __forceinline__ c2 cmul2(c2 a, tw2 w) {
    c2 o;
    o.re = fma2(a.re, w.r, mul2(a.im, w.in));
    o.im = fma2(a.re, w.i, mul2(a.im, w.r));
    return o;
}
__device__ __forceinline__ void radix4p(c2& a0, c2& a1, c2& a2, c2& a3,
                                        tw2 w1, tw2 w2, tw2 w3) {
    c2 b1 = cmul2(a1, w1);
    c2 b2 = cmul2(a2, w2);
    c2 b3 = cmul2(a3, w3);
    ull t0r = add2(a0.re, b2.re), t0i = add2(a0.im, b2.im);
    ull t1r = sub2(a0.re, b2.re), t1i = sub2(a0.im, b2.im);
    ull t2r = add2(b1.re, b3.re), t2i = add2(b1.im, b3.im);
    ull t3r = sub2(b1.im, b3.im), t3i = sub2(b3.re, b1.re);   // -i*(b1-b3)
    a0.re = add2(t0r, t2r); a0.im = add2(t0i, t2i);
    a1.re = add2(t1r, t3r); a1.im = add2(t1i, t3i);
    a2.re = sub2(t0r, t2r); a2.im = sub2(t0i, t2i);
    a3.re = sub2(t1r, t3r); a3.im = sub2(t1i, t3i);
}
__device__ __forceinline__ void radix4p_nt(c2& a0, c2& a1, c2& a2, c2& a3) {
    ull t0r = add2(a0.re, a2.re), t0i = add2(a0.im, a2.im);
    ull t1r = sub2(a0.re, a2.re), t1i = sub2(a0.im, a2.im);
    ull t2r = add2(a1.re, a3.re), t2i = add2(a1.im, a3.im);
    ull t3r = sub2(a1.im, a3.im), t3i = sub2(a3.re, a1.re);
    a0.re = add2(t0r, t2r); a0.im = add2(t0i, t2i);
    a1.re = add2(t1r, t3r); a1.im = add2(t1i, t3i);
    a2.re = sub2(t0r, t2r); a2.im = sub2(t0i, t2i);
    a3.re = sub2(t1r, t3r); a3.im = sub2(t1i, t3i);
}
__device__ __forceinline__ c2 ld4(const float4* p) {
    float4 v = *p;
    c2 a; a.re = pk2(v.x, v.y); a.im = pk2(v.z, v.w); return a;
}
__device__ __forceinline__ void st4(float4* p, c2 a) {
    float4 v;
    upk2(v.x, v.y, a.re);
    upk2(v.z, v.w, a.im);
    *p = v;
}

__device__ __forceinline__ float sqrt_approx(float x) {
    float r; asm("sqrt.approx.f32 %0, %1;" : "=f"(r) : "f"(x)); return r;
}
__device__ __forceinline__ float lg2_approx(float x) {
    float r; asm("lg2.approx.f32 %0, %1;" : "=f"(r) : "f"(x)); return r;
}
__device__ __forceinline__ float ex2_approx(float x) {
    float r; asm("ex2.approx.f32 %0, %1;" : "=f"(r) : "f"(x)); return r;
}
__device__ __forceinline__ int reflect_idx(int j) {
    return (j < 0) ? -j : ((j >= WLEN) ? 2 * WLEN - 2 - j : j);
}

// real-FFT unpack for pair (k, 1024-k): a = z[k], cc = z[1024-k], w = exp(-i*pi*k/1024)
__device__ __forceinline__ void unpack_pair(c2 a, c2 cc, float2 w, ull* __restrict__ pw, int k) {
    ull EX = add2(a.re, cc.re);
    ull EY = sub2(a.im, cc.im);
    ull OX = add2(a.im, cc.im);
    ull OY = sub2(cc.re, a.re);
    ull wx = bc2(w.x), wy = bc2(w.y);
    ull RW = sub2(mul2(OX, wx), mul2(OY, wy));
    ull IW = fma2(OX, wy, mul2(OY, wx));
    ull Xr = add2(EX, RW), Xi = add2(EY, IW);
    ull Yr = sub2(EX, RW), Yi = sub2(IW, EY);
    const ull Q = bc2(0.25f);
    pw[k]        = mul2(fma2(Xi, Xi, mul2(Xr, Xr)), Q);
    pw[1024 - k] = mul2(fma2(Yi, Yi, mul2(Yr, Yr)), Q);
}

// stage-4 butterfly p (loads z[p+256q], applies twiddles, leaves outputs in v[q])
__device__ __forceinline__ void s4_bfly(const float4* __restrict__ zz, int p, float2 w, c2 v[4]) {
    const int o = SK2(p);   // SK2(p+256q) = SK2(p) + 272q  (p < 256)
    v[0] = ld4(&zz[o]);
    v[1] = ld4(&zz[o + 272]);
    v[2] = ld4(&zz[o + 544]);
    v[3] = ld4(&zz[o + 816]);
    float2 w2 = cmul(w, w);
    float2 w3 = cmul(w2, w);
    radix4p(v[0], v[1], v[2], v[3], mktw(w), mktw(w2), mktw(w3));
}

// ---------------- fused frame+window+FFT+power+mel, 2 frames SIMD-packed ----------------
// 64 threads per block; one frame PAIR per block; 16 complex points x 2 frames per thread.
__global__ __launch_bounds__(64, 8) void melspec_kernel(const float* __restrict__ wave) {
    __shared__ float4 zz[ZLEN4];       // (reA, reB, imA, imB)  17.5 KB
    __shared__ ull    pw[1056];        // (pwA, pwB) per bin     8.4 KB
    __shared__ float  fp[NPTS];

    const int T  = threadIdx.x;        // 0..63
    const int gA = blockIdx.x * 2;
    const int gB = gA + 1;
    const int bA = gA / NFRM, tA = gA - bA * NFRM;
    const int bB = gB / NFRM, tB = gB - bB * NFRM;

    // mel breakpoints
    for (int i = T; i < NPTS; i += 64) {
        const float mlo = 2595.0f * log10f(1.0f + 20.0f / 700.0f);
        const float mhi = 2595.0f * log10f(1.0f + 16000.0f / 700.0f);
        float m = mlo + (mhi - mlo) * (float)i / (float)(NPTS - 1);
        fp[i] = 700.0f * (exp10f(m / 2595.0f) - 1.0f);
    }

    const float* __restrict__ wbA = wave + (size_t)bA * WLEN;
    const float* __restrict__ wbB = wave + (size_t)bB * WLEN;
    const int p0A = tA * HOP - (NFFT / 2);
    const int p0B = tB * HOP - (NFFT / 2);

    // ---- fused gmem gather (digit-reversed) + Hann window + stages 0+1 ----
    // thread T's stage-0 butterflies: old index 4T+jj -> rj = 64*jj + rev4(T);
    // gathers z[rj + 256q] straight from gmem (no staging round trip).
    {
        const int rev4T = ((T & 3) << 4) | (((T >> 2) & 3) << 2) | (T >> 4);

        // window rotor: theta(n) = pi*n/512 (n = complex index);
        // per-q step: dn=256 -> dtheta = pi/2 (free (c,s)->(-s,c) swap)
        // per-jj step: dn=64  -> dtheta = pi/8
        // w1 angle = theta + pi/1024 (odd real sample)
        float s0, c0;
        __sincosf((float)M_PI * (float)rev4T / 512.0f, &s0, &c0);
        const float CP8 = 0.92387953251128674f, SP8 = 0.38268343236508977f;   // cos/sin(pi/8)
        const float CCW = 0.9999952938095760f,  SCW = 0.0030679567629659760f; // cos/sin(pi/1024)

        const bool interior = (p0A >= 0) && (p0B + NFFT <= WLEN) && (bA == bB);
        const float2* __restrict__ wvA = (const float2*)(wbA + p0A);
        const float2* __restrict__ wvB = (const float2*)(wbB + p0B);

        c2 y[4][4];   // y[jj][q->p]
        float cj = c0, sj = s0;
        #pragma unroll
        for (int jj = 0; jj < 4; jj++) {
            const int nbase = rev4T + 64 * jj;
            float cq = cj, sq = sj;
            c2 a[4];
            #pragma unroll
            for (int q = 0; q < 4; q++) {
                const int n = nbase + 256 * q;
                float vAx, vAy, vBx, vBy;
                if (interior) {
                    float2 vA = wvA[n];
                    float2 vB = wvB[n];
                    vAx = vA.x; vAy = vA.y; vBx = vB.x; vBy = vB.y;
                } else {
                    int jA = p0A + 2 * n, jB = p0B + 2 * n;
                    vAx = wbA[reflect_idx(jA)];     vBx = wbB[reflect_idx(jB)];
                    vAy = wbA[reflect_idx(jA + 1)]; vBy = wbB[reflect_idx(jB + 1)];
                }
                float w0 = 0.5f - 0.5f * cq;
                float w1 = 0.5f - 0.5f * (cq * CCW - sq * SCW);
                a[q].re = pk2(vAx * w0, vBx * w0);
                a[q].im = pk2(vAy * w1, vBy * w1);
                float tmp = cq; cq = -sq; sq = tmp;     // rotate pi/2
            }
            radix4p_nt(a[0], a[1], a[2], a[3]);
            y[jj][0] = a[0]; y[jj][1] = a[1]; y[jj][2] = a[2]; y[jj][3] = a[3];
            float tc = cj * CP8 - sj * SP8;             // rotate pi/8
            sj = cj * SP8 + sj * CP8;
            cj = tc;
        }

        // stage 1: butterfly over jj for each p, twiddles W16^p (constants)
        const float2 W16_1[4] = { {1.f,0.f}, {0.92387953251f,-0.38268343236f},
                                  {0.70710678119f,-0.70710678119f}, {0.38268343236f,-0.92387953251f} };
        const float2 W16_2[4] = { {1.f,0.f}, {0.70710678119f,-0.70710678119f},
                                  {0.f,-1.f}, {-0.70710678119f,-0.70710678119f} };
        const float2 W16_3[4] = { {1.f,0.f}, {0.38268343236f,-0.92387953251f},
                                  {-0.70710678119f,-0.70710678119f}, {-0.92387953251f,0.38268343236f} };
        #pragma unroll
        for (int p = 0; p < 4; p++)
            radix4p(y[0][p], y[1][p], y[2][p], y[3][p],
                    mktw(W16_1[p]), mktw(W16_2[p]), mktw(W16_3[p]));

        const int st = 17 * T;   // SK2(16T + c) = 17T + c, c < 16
        #pragma unroll
        for (int q = 0; q < 4; q++)
            #pragma unroll
            for (int p = 0; p < 4; p++)
                st4(&zz[st + p + 4 * q], y[q][p]);
    }
    __syncthreads();

    // ---- merged stages 2+3: thread owns {256C + 16u + j0}, in place ----
    {
        const int C  = T >> 4;
        const int j0 = T & 15;
        const int base = 272 * C + j0;   // SK2(256C + j0); +17 per u
        c2 v[16];
        #pragma unroll
        for (int u = 0; u < 16; u++)
            v[u] = ld4(&zz[base + 17 * u]);

        // stage 2: twiddle exp(-2*pi*i*j0/64)
        {
            float s, c;
            __sincosf(-(float)M_PI * (float)j0 / 32.0f, &s, &c);
            float2 w1 = make_float2(c, s);
            float2 w2 = cmul(w1, w1);
            float2 w3 = cmul(w2, w1);
            tw2 t1 = mktw(w1), t2 = mktw(w2), t3 = mktw(w3);
            #pragma unroll
            for (int a = 0; a < 4; a++)
                radix4p(v[4*a+0], v[4*a+1], v[4*a+2], v[4*a+3], t1, t2, t3);
        }
        // stage 3: w1(bq) = exp(-2*pi*i*(16bq + j0)/256) via rotor
        {
            float s, c;
            __sincosf(-(float)M_PI * (float)j0 / 128.0f, &s, &c);
            float2 w = make_float2(c, s);
            const float2 STEP3 = make_float2(0.9238795325112867f, -0.3826834323650898f); // exp(-i pi/8)
            #pragma unroll
            for (int bq = 0; bq < 4; bq++) {
                float2 w2 = cmul(w, w);
                float2 w3 = cmul(w2, w);
                radix4p(v[bq], v[4+bq], v[8+bq], v[12+bq], mktw(w), mktw(w2), mktw(w3));
                w = cmul(w, STEP3);
            }
        }
        #pragma unroll
        for (int u = 0; u < 16; u++)
            st4(&zz[base + 17 * u], v[u]);
    }
    __syncthreads();

    // ---- stage 4 + real-FFT unpack fused in registers ----
    // thread T owns the pairing-closed butterfly set {T, 256-T, 127-T, 129+T}
    {
        // stage-4 twiddles: w(p) = exp(-2*pi*i*p/1024)
        float s4, c4;
        __sincosf(-(float)M_PI * (float)T / 512.0f, &s4, &c4);
        float2 wA = make_float2(c4, s4);                       // w(T)
        const float2 c1s = make_float2(0.9999811752826011f, -0.0061358846491544753f); // w(1)
        float2 wT1 = cmul(wA, c1s);                            // w(T+1)
        const float R2 = 0.70710678118654752f;
        const float2 K4 = make_float2(R2, -R2);                // exp(-i pi/4) = w(128) = wh(256)
        float2 wB = (T == 0) ? K4 : make_float2(-wA.y, -wA.x); // w(256-T); T=0 -> w(128)
        float2 wC = cmul(K4, make_float2(wT1.x, -wT1.y));      // w(127-T)
        float2 wD = cmul(K4, wT1);                             // w(129+T)

        // unpack half-twiddles: wh(p) = exp(-i*pi*p/1024)
        float hs, hc;
        __sincosf(-(float)M_PI * (float)T / 1024.0f, &hs, &hc);
        float2 whA = make_float2(hc, hs);                      // wh(T)
        const float2 ch1 = make_float2(0.9999952938095760f, -0.0030679567629659760f); // wh(1)
        float2 whT1 = cmul(whA, ch1);                          // wh(T+1)
        const float2 K8 = make_float2(0.92387953251128674f, -0.38268343236508977f);   // wh(128) = exp(-i pi/8)
        float2 whC = cmul(K8, make_float2(whT1.x, -whT1.y));   // wh(127-T)

        const float2 Cq[4] = { {1.f, 0.f}, {R2, -R2}, {0.f, -1.f}, {-R2, -R2} };  // wh(256q)

        const int pA = T;
        const int pB = (T == 0) ? 128 : 256 - T;
        const int pC = 127 - T;
        const int pD = 129 + T;

        // group 1: butterflies pA, pB
        {
            c2 vA[4], vB[4];
            s4_bfly(zz, pA, wA, vA);
            s4_bfly(zz, pB, wB, vB);
            if (T == 0) {
                ull x0 = add2(vA[0].re, vA[0].im);
                ull x1 = sub2(vA[0].re, vA[0].im);
                pw[0]    = mul2(x0, x0);
                pw[1024] = mul2(x1, x1);
                unpack_pair(vA[1], vA[3], K4,                     pw, 256);
                unpack_pair(vA[2], vA[2], make_float2(0.f, -1.f), pw, 512);
                unpack_pair(vB[0], vB[3], K8,                     pw, 128);
                unpack_pair(vB[1], vB[2], cmul(K8, Cq[1]),        pw, 384);
            } else {
                #pragma unroll
                for (int q = 0; q < 4; q++)
                    unpack_pair(vA[q], vB[3 - q], cmul(whA, Cq[q]), pw, pA + 256 * q);
            }
        }
        // group 2: butterflies pC, pD (uniform for all threads)
        {
            c2 vC[4], vD[4];
            s4_bfly(zz, pC, wC, vC);
            s4_bfly(zz, pD, wD, vD);
            #pragma unroll
            for (int q = 0; q < 4; q++)
                unpack_pair(vC[q], vD[3 - q], cmul(whC, Cq[q]), pw, pC + 256 * q);
        }
    }
    __syncthreads();

    // ---- mel projection: thread T does mels T and 127-T, both frames packed ----
    {
        const float df = 16000.0f / 1024.0f;
        #pragma unroll
        for (int h = 0; h < 2; h++) {
            int m = h ? (127 - T) : T;
            float f0 = fp[m];
            float f1 = fp[m + 1];
            float f2 = fp[m + 2];
            float inv_d0 = 1.0f / (f1 - f0);
            float inv_d1 = 1.0f / (f2 - f1);
            int klo = max(0, (int)(f0 / df));
            int khi = min(1024, (int)(f2 / df) + 1);
            ull acc = bc2(0.0f);
            float freq = (float)klo * df;
            for (int k = klo; k <= khi; k++) {
                float wgt = fminf((freq - f0) * inv_d0, (f2 - freq) * inv_d1);
                wgt = fmaxf(wgt, 0.0f);
                acc = fma2(pw[k], bc2(wgt), acc);
                freq += df;
            }
            float aA, aB;
            upk2(aA, aB, acc);
            g_mel[((size_t)bA * NFRM + tA) * NMELS + m] = aA;
            g_mel[((size_t)bB * NFRM + tB) * NMELS + m] = aB;
        }
    }
}

// ---------------- PCEN pass A: per-chunk partial IIR (m0 = 0) ----------------
__global__ __launch_bounds__(128) void pcen_partial_kernel() {
    const int b = blockIdx.x;
    const int c = blockIdx.y;
    const int m = threadIdx.x;
    const int t0 = c * CHLEN;
    const int len = min(CHLEN, NFRM - t0);

    const float* __restrict__ src = g_mel + ((size_t)b * NFRM + t0) * NMELS + m;
    float p = 0.0f;
    for (int k = 0; k < len; k++) {
        float x = src[(size_t)k * NMELS];
        p = fmaf(0.975f, p, 0.025f * x);
    }
    g_part[((size_t)b * NCHUNK + c) * NMELS + m] = p;
}

// ---------------- PCEN pass B: reconstruct state, emit outputs ----------------
__global__ __launch_bounds__(128) void pcen_out_kernel(float* __restrict__ out) {
    __shared__ float sm[NMELS * (CHLEN + 1)];

    const int b = blockIdx.x;
    const int c = blockIdx.y;
    const int m = threadIdx.x;
    const int t0 = c * CHLEN;
    const int len = min(CHLEN, NFRM - t0);

    float pow40 = 1.0f;
    #pragma unroll
    for (int i = 0; i < CHLEN; i++) pow40 *= 0.975f;

    const float* __restrict__ part = g_part + (size_t)b * NCHUNK * NMELS + m;
    float mst = 0.0f;
    for (int cp = 0; cp < c; cp++)
        mst = fmaf(mst, pow40, part[(size_t)cp * NMELS]);

    const float EPS = 1e-6f;
    const float ALPHA = 0.98f;
    const float DELTA = 2.0f;
    const float DELTA_R = 1.41421356237309515f;

    const float* __restrict__ src = g_mel + ((size_t)b * NFRM + t0) * NMELS + m;
    float* __restrict__ row = sm + (size_t)m * (CHLEN + 1);

    for (int k = 0; k < len; k++) {
        float x = src[(size_t)k * NMELS];
        mst = fmaf(0.975f, mst, 0.025f * x);
        float d = ex2_approx(-ALPHA * lg2_approx(EPS + mst));
        row[k] = sqrt_approx(fmaf(x, d, DELTA)) - DELTA_R;
    }
    __syncthreads();

    float* __restrict__ dst = out + (size_t)b * NMELS * NFRM + t0;
    const int total = NMELS * len;
    for (int j = m; j < total; j += NMELS) {
        int mr = j / len;
        int tt = j - mr * len;
        dst[(size_t)mr * NFRM + tt] = sm[(size_t)mr * (CHLEN + 1) + tt];
    }
}

extern "C" void kernel_launch(void* const* d_in, const int* in_sizes, int n_in,
                              void* d_out, int out_size) {
    const float* wave = (const float*)d_in[0];
    float* out = (float*)d_out;

    melspec_kernel<<<(BATCH * NFRM) / 2, 64>>>(wave);   // 10016 blocks, 1 frame-pair each

    dim3 pgrid(BATCH, NCHUNK);
    pcen_partial_kernel<<<pgrid, NMELS>>>();
    pcen_out_kernel<<<pgrid, NMELS>>>(out);
}

// round 13
// speedup vs baseline: 1.0027x; 1.0027x over previous
#include <cuda_runtime.h>
#include <math.h>

#define BATCH 64
#define WLEN  160000
#define NFRM  313          // 1 + 160000/512
#define HOP   512
#define NFFT  2048
#define MHALF 1024         // complex FFT length
#define NMELS 128
#define NPTS  130          // mel breakpoints

#define SK2(i) ((i) + ((i) >> 4))    // skew (slots are float4)
#define ZLEN4  1092                  // SK2(1024)=1088 < 1092

#define NCHUNK 8
#define CHLEN  40                    // 7*40 + 33 = 313

typedef unsigned long long ull;

__device__ float g_mel[BATCH * NFRM * NMELS];    // mel power, layout [b][t][m]
__device__ float g_part[BATCH * NCHUNK * NMELS]; // per-chunk partial IIR sums

// ---------------- packed f32x2 helpers ----------------
__device__ __forceinline__ ull pk2(float lo, float hi) {
    ull r; asm("mov.b64 %0, {%1, %2};" : "=l"(r) : "f"(lo), "f"(hi)); return r;
}
__device__ __forceinline__ ull bc2(float v) { return pk2(v, v); }
__device__ __forceinline__ void upk2(float& lo, float& hi, ull v) {
    asm("mov.b64 {%0, %1}, %2;" : "=f"(lo), "=f"(hi) : "l"(v));
}
__device__ __forceinline__ ull add2(ull a, ull b) {
    ull r; asm("add.rn.f32x2 %0, %1, %2;" : "=l"(r) : "l"(a), "l"(b)); return r;
}
__device__ __forceinline__ ull sub2(ull a, ull b) {
    ull r; asm("sub.rn.f32x2 %0, %1, %2;" : "=l"(r) : "l"(a), "l"(b)); return r;
}
__device__ __forceinline__ ull mul2(ull a, ull b) {
    ull r; asm("mul.rn.f32x2 %0, %1, %2;" : "=l"(r) : "l"(a), "l"(b)); return r;
}
__device__ __forceinline__ ull fma2(ull a, ull b, ull c) {
    ull r; asm("fma.rn.f32x2 %0, %1, %2, %3;" : "=l"(r) : "l"(a), "l"(b), "l"(c)); return r;
}

struct c2  { ull re, im; };                 // complex, 2 frames packed per component
struct tw2 { ull r, i, in; };               // packed twiddle

__device__ __forceinline__ float2 cmul(float2 a, float2 b) {
    return make_float2(a.x * b.x - a.y * b.y, a.x * b.y + a.y * b.x);
}
__device__ __forceinline__ tw2 mktw(float2 w) {
    tw2 t; t.r = bc2(w.x); t.i = bc2(w.y); t.in = bc2(-w.y); return t;
}
__device__ __forceinline__ c2 cmul2(c2 a, tw2 w) {
    c2 o;
    o.re = fma2(a.re, w.r, mul2(a.im, w.in));
    o.im = fma2(a.re, w.i, mul2(a.im, w.r));
    return o;
}
__device__ __forceinline__ void radix4p(c2& a0, c2& a1, c2& a2, c2& a3,
                                        tw2 w1, tw2 w2, tw2 w3) {
    c2 b1 = cmul2(a1, w1);
    c2 b2 = cmul2(a2, w2);
    c2 b3 = cmul2(a3, w3);
    ull t0r = add2(a0.re, b2.re), t0i = add2(a0.im, b2.im);
    ull t1r = sub2(a0.re, b2.re), t1i = sub2(a0.im, b2.im);
    ull t2r = add2(b1.re, b3.re), t2i = add2(b1.im, b3.im);
    ull t3r = sub2(b1.im, b3.im), t3i = sub2(b3.re, b1.re);   // -i*(b1-b3)
    a0.re = add2(t0r, t2r); a0.im = add2(t0i, t2i);
    a1.re = add2(t1r, t3r); a1.im = add2(t1i, t3i);
    a2.re = sub2(t0r, t2r); a2.im = sub2(t0i, t2i);
    a3.re = sub2(t1r, t3r); a3.im = sub2(t1i, t3i);
}
__device__ __forceinline__ void radix4p_nt(c2& a0, c2& a1, c2& a2, c2& a3) {
    ull t0r = add2(a0.re, a2.re), t0i = add2(a0.im, a2.im);
    ull t1r = sub2(a0.re, a2.re), t1i = sub2(a0.im, a2.im);
    ull t2r = add2(a1.re, a3.re), t2i = add2(a1.im, a3.im);
    ull t3r = sub2(a1.im, a3.im), t3i = sub2(a3.re, a1.re);
    a0.re = add2(t0r, t2r); a0.im = add2(t0i, t2i);
    a1.re = add2(t1r, t3r); a1.im = add2(t1i, t3i);
    a2.re = sub2(t0r, t2r); a2.im = sub2(t0i, t2i);
    a3.re = sub2(t1r, t3r); a3.im = sub2(t1i, t3i);
}
__device__ __forceinline__ c2 ld4(const float4* p) {
    float4 v = *p;
    c2 a; a.re = pk2(v.x, v.y); a.im = pk2(v.z, v.w); return a;
}
__device__ __forceinline__ void st4(float4* p, c2 a) {
    float4 v;
    upk2(v.x, v.y, a.re);
    upk2(v.z, v.w, a.im);
    *p = v;
}

__device__ __forceinline__ float sqrt_approx(float x) {
    float r; asm("sqrt.approx.f32 %0, %1;" : "=f"(r) : "f"(x)); return r;
}
__device__ __forceinline__ float lg2_approx(float x) {
    float r; asm("lg2.approx.f32 %0, %1;" : "=f"(r) : "f"(x)); return r;
}
__device__ __forceinline__ float ex2_approx(float x) {
    float r; asm("ex2.approx.f32 %0, %1;" : "=f"(r) : "f"(x)); return r;
}
__device__ __forceinline__ int reflect_idx(int j) {
    return (j < 0) ? -j : ((j >= WLEN) ? 2 * WLEN - 2 - j : j);
}

// ---- power spectrum overlaid in zz: pw[k] lives in the first 8 bytes of zz[SK2(k)] ----
__device__ __forceinline__ void pw_st(float4* zz, int k, ull v) {
    *reinterpret_cast<ull*>(&zz[SK2(k)]) = v;
}
__device__ __forceinline__ ull pw_ld(const float4* zz, int k) {
    return *reinterpret_cast<const ull*>(&zz[SK2(k)]);
}

// real-FFT unpack for pair (k, 1024-k): a = z[k], cc = z[1024-k], w = exp(-i*pi*k/1024)
__device__ __forceinline__ void unpack_pair(c2 a, c2 cc, float2 w, float4* __restrict__ zz, int k) {
    ull EX = add2(a.re, cc.re);
    ull EY = sub2(a.im, cc.im);
    ull OX = add2(a.im, cc.im);
    ull OY = sub2(cc.re, a.re);
    ull wx = bc2(w.x), wy = bc2(w.y);
    ull RW = sub2(mul2(OX, wx), mul2(OY, wy));
    ull IW = fma2(OX, wy, mul2(OY, wx));
    ull Xr = add2(EX, RW), Xi = add2(EY, IW);
    ull Yr = sub2(EX, RW), Yi = sub2(IW, EY);
    const ull Q = bc2(0.25f);
    pw_st(zz, k,        mul2(fma2(Xi, Xi, mul2(Xr, Xr)), Q));
    pw_st(zz, 1024 - k, mul2(fma2(Yi, Yi, mul2(Yr, Yr)), Q));
}

// stage-4 butterfly p: LOAD only (compute deferred past the sync)
__device__ __forceinline__ void s4_load(const float4* __restrict__ zz, int p, c2 v[4]) {
    const int o = SK2(p);   // SK2(p+256q) = SK2(p) + 272q  (p < 256)
    v[0] = ld4(&zz[o]);
    v[1] = ld4(&zz[o + 272]);
    v[2] = ld4(&zz[o + 544]);
    v[3] = ld4(&zz[o + 816]);
}
__device__ __forceinline__ void s4_compute(float2 w, c2 v[4]) {
    float2 w2 = cmul(w, w);
    float2 w3 = cmul(w2, w);
    radix4p(v[0], v[1], v[2], v[3], mktw(w), mktw(w2), mktw(w3));
}

// ---------------- fused frame+window+FFT+power+mel, 2 frames SIMD-packed ----------------
// 64 threads per block; one frame PAIR per block; 16 complex points x 2 frames per thread.
__global__ __launch_bounds__(64, 10) void melspec_kernel(const float* __restrict__ wave) {
    __shared__ float4 zz[ZLEN4];       // (reA, reB, imA, imB); later overlaid with power  17.5 KB
    __shared__ float  fp[NPTS];

    const int T  = threadIdx.x;        // 0..63
    const int gA = blockIdx.x * 2;
    const int gB = gA + 1;
    const int bA = gA / NFRM, tA = gA - bA * NFRM;
    const int bB = gB / NFRM, tB = gB - bB * NFRM;

    const int skT = T + (T >> 4);      // SK2(T)

    // mel breakpoints
    for (int i = T; i < NPTS; i += 64) {
        const float mlo = 2595.0f * log10f(1.0f + 20.0f / 700.0f);
        const float mhi = 2595.0f * log10f(1.0f + 16000.0f / 700.0f);
        float m = mlo + (mhi - mlo) * (float)i / (float)(NPTS - 1);
        fp[i] = 700.0f * (exp10f(m / 2595.0f) - 1.0f);
    }

    // ---- staging: frames (reflect pad) * Hann; window rotor shared by both lanes ----
    const float* __restrict__ wbA = wave + (size_t)bA * WLEN;
    const float* __restrict__ wbB = wave + (size_t)bB * WLEN;
    const int p0A = tA * HOP - (NFFT / 2);
    const int p0B = tB * HOP - (NFFT / 2);
    const float CW = (float)M_PI / 1024.0f;
    float rs, rc;
    __sincosf(CW * (float)(2 * T), &rs, &rc);
    float2 rot = make_float2(rc, rs);
    // per-e step: dn = 64 complex = 128 real samples -> dtheta = CW*128 = pi/8
    const float2 RSTEP = make_float2(0.9238795325112867f, 0.3826834323650898f);   // exp(+i pi/8)
    const float CCW = 0.9999952938095760f;     // cos(pi/1024)
    const float SCW = 0.0030679567629659760f;  // sin(pi/1024)

    if (p0A >= 0 && p0B + NFFT <= WLEN && bA == bB) {
        const float2* __restrict__ wvA = (const float2*)(wbA + p0A) + T;
        const float2* __restrict__ wvB = (const float2*)(wbB + p0B) + T;
        #pragma unroll
        for (int e = 0; e < 16; e++) {
            float2 vA = wvA[64 * e];
            float2 vB = wvB[64 * e];
            float c1 = rot.x * CCW - rot.y * SCW;
            float w0 = 0.5f - 0.5f * rot.x;
            float w1 = 0.5f - 0.5f * c1;
            c2 z; z.re = pk2(vA.x * w0, vB.x * w0); z.im = pk2(vA.y * w1, vB.y * w1);
            st4(&zz[skT + 68 * e], z);
            rot = cmul(rot, RSTEP);
        }
    } else {
        #pragma unroll
        for (int e = 0; e < 16; e++) {
            int n = T + 64 * e;
            int jA = p0A + 2 * n, jB = p0B + 2 * n;
            float vAx = wbA[reflect_idx(jA)],     vBx = wbB[reflect_idx(jB)];
            float vAy = wbA[reflect_idx(jA + 1)], vBy = wbB[reflect_idx(jB + 1)];
            float c1 = rot.x * CCW - rot.y * SCW;
            float w0 = 0.5f - 0.5f * rot.x;
            float w1 = 0.5f - 0.5f * c1;
            c2 z; z.re = pk2(vAx * w0, vBx * w0); z.im = pk2(vAy * w1, vBy * w1);
            st4(&zz[skT + 68 * e], z);
            rot = cmul(rot, RSTEP);
        }
    }
    __syncthreads();

    // ---- merged stages 0+1: outputs [16T, 16T+16) ----
    {
        c2 y[4][4];   // y[j][p]
        #pragma unroll
        for (int j = 0; j < 4; j++) {
            unsigned old = (unsigned)(4 * T + j);
            unsigned rj = __brev(old) >> 24;
            rj = ((rj & 0x55u) << 1) | ((rj >> 1) & 0x55u);   // base-4 digit reverse
            int skrj = (int)rj + ((int)rj >> 4);
            c2 a0 = ld4(&zz[skrj]);
            c2 a1 = ld4(&zz[skrj + 272]);
            c2 a2 = ld4(&zz[skrj + 544]);
            c2 a3 = ld4(&zz[skrj + 816]);
            radix4p_nt(a0, a1, a2, a3);
            y[j][0] = a0; y[j][1] = a1; y[j][2] = a2; y[j][3] = a3;
        }
        __syncthreads();   // all gathers complete block-wide before any store

        const float2 W16_1[4] = { {1.f,0.f}, {0.92387953251f,-0.38268343236f},
                                  {0.70710678119f,-0.70710678119f}, {0.38268343236f,-0.92387953251f} };
        const float2 W16_2[4] = { {1.f,0.f}, {0.70710678119f,-0.70710678119f},
                                  {0.f,-1.f}, {-0.70710678119f,-0.70710678119f} };
        const float2 W16_3[4] = { {1.f,0.f}, {0.38268343236f,-0.92387953251f},
                                  {-0.70710678119f,-0.70710678119f}, {-0.92387953251f,0.38268343236f} };
        #pragma unroll
        for (int p = 0; p < 4; p++)
            radix4p(y[0][p], y[1][p], y[2][p], y[3][p],
                    mktw(W16_1[p]), mktw(W16_2[p]), mktw(W16_3[p]));

        const int st = 17 * T;   // SK2(16T + c) = 17T + c, c < 16
        #pragma unroll
        for (int q = 0; q < 4; q++)
            #pragma unroll
            for (int p = 0; p < 4; p++)
                st4(&zz[st + p + 4 * q], y[q][p]);
    }
    __syncthreads();

    // ---- merged stages 2+3: thread owns {256C + 16u + j0}, in place ----
    {
        const int C  = T >> 4;
        const int j0 = T & 15;
        const int base = 272 * C + j0;   // SK2(256C + j0); +17 per u
        c2 v[16];
        #pragma unroll
        for (int u = 0; u < 16; u++)
            v[u] = ld4(&zz[base + 17 * u]);

        // stage 2: twiddle exp(-2*pi*i*j0/64)
        {
            float s, c;
            __sincosf(-(float)M_PI * (float)j0 / 32.0f, &s, &c);
            float2 w1 = make_float2(c, s);
            float2 w2 = cmul(w1, w1);
            float2 w3 = cmul(w2, w1);
            tw2 t1 = mktw(w1), t2 = mktw(w2), t3 = mktw(w3);
            #pragma unroll
            for (int a = 0; a < 4; a++)
                radix4p(v[4*a+0], v[4*a+1], v[4*a+2], v[4*a+3], t1, t2, t3);
        }
        // stage 3: w1(bq) = exp(-2*pi*i*(16bq + j0)/256) via rotor (dn=16 -> dtheta=pi/8)
        {
            float s, c;
            __sincosf(-(float)M_PI * (float)j0 / 128.0f, &s, &c);
            float2 w = make_float2(c, s);
            const float2 STEP3 = make_float2(0.9238795325112867f, -0.3826834323650898f); // exp(-i pi/8)
            #pragma unroll
            for (int bq = 0; bq < 4; bq++) {
                float2 w2 = cmul(w, w);
                float2 w3 = cmul(w2, w);
                radix4p(v[bq], v[4+bq], v[8+bq], v[12+bq], mktw(w), mktw(w2), mktw(w3));
                w = cmul(w, STEP3);
            }
        }
        #pragma unroll
        for (int u = 0; u < 16; u++)
            st4(&zz[base + 17 * u], v[u]);
    }
    __syncthreads();

    // ---- stage 4 + real-FFT unpack fused in registers; power OVERLAID into zz ----
    // thread T owns the pairing-closed butterfly set {T, 256-T, 127-T, 129+T}.
    // Slot-residue proof (mod 256): group1 touches residues [0,63]U[193,255] (+slot 1024),
    // group2 touches residues [64,127]U[129,192] -- disjoint, so g1 pw-writes cannot
    // clobber g2 zz-reads. Syncs separate loads from writes within each group.
    {
        // stage-4 twiddles: w(p) = exp(-2*pi*i*p/1024)
        float s4, c4;
        __sincosf(-(float)M_PI * (float)T / 512.0f, &s4, &c4);
        float2 wA = make_float2(c4, s4);                       // w(T)
        const float2 c1s = make_float2(0.9999811752826011f, -0.0061358846491544753f); // w(1)
        float2 wT1 = cmul(wA, c1s);                            // w(T+1)
        const float R2 = 0.70710678118654752f;
        const float2 K4 = make_float2(R2, -R2);                // exp(-i pi/4) = w(128) = wh(256)
        float2 wB = (T == 0) ? K4 : make_float2(-wA.y, -wA.x); // w(256-T); T=0 -> w(128)
        float2 wC = cmul(K4, make_float2(wT1.x, -wT1.y));      // w(127-T)
        float2 wD = cmul(K4, wT1);                             // w(129+T)

        // unpack half-twiddles: wh(p) = exp(-i*pi*p/1024)
        float hs, hc;
        __sincosf(-(float)M_PI * (float)T / 1024.0f, &hs, &hc);
        float2 whA = make_float2(hc, hs);                      // wh(T)
        const float2 ch1 = make_float2(0.9999952938095760f, -0.0030679567629659760f); // wh(1)
        float2 whT1 = cmul(whA, ch1);                          // wh(T+1)
        const float2 K8 = make_float2(0.92387953251128674f, -0.38268343236508977f);   // wh(128) = exp(-i pi/8)
        float2 whC = cmul(K8, make_float2(whT1.x, -whT1.y));   // wh(127-T)

        const float2 Cq[4] = { {1.f, 0.f}, {R2, -R2}, {0.f, -1.f}, {-R2, -R2} };  // wh(256q)

        const int pA = T;
        const int pB = (T == 0) ? 128 : 256 - T;
        const int pC = 127 - T;
        const int pD = 129 + T;

        // group 1: butterflies pA, pB
        {
            c2 vA[4], vB[4];
            s4_load(zz, pA, vA);
            s4_load(zz, pB, vB);
            __syncthreads();           // all g1 reads done before any g1 pw write
            s4_compute(wA, vA);
            s4_compute(wB, vB);
            if (T == 0) {
                ull x0 = add2(vA[0].re, vA[0].im);
                ull x1 = sub2(vA[0].re, vA[0].im);
                pw_st(zz, 0,    mul2(x0, x0));
                pw_st(zz, 1024, mul2(x1, x1));
                unpack_pair(vA[1], vA[3], K4,                     zz, 256);
                unpack_pair(vA[2], vA[2], make_float2(0.f, -1.f), zz, 512);
                unpack_pair(vB[0], vB[3], K8,                     zz, 128);
                unpack_pair(vB[1], vB[2], cmul(K8, Cq[1]),        zz, 384);
            } else {
                #pragma unroll
                for (int q = 0; q < 4; q++)
                    unpack_pair(vA[q], vB[3 - q], cmul(whA, Cq[q]), zz, pA + 256 * q);
            }
        }
        // group 2: butterflies pC, pD (slots disjoint from all g1 pw writes)
        {
            c2 vC[4], vD[4];
            s4_load(zz, pC, vC);
            s4_load(zz, pD, vD);
            __syncthreads();           // all g2 reads done before any g2 pw write
            s4_compute(wC, vC);
            s4_compute(wD, vD);
            #pragma unroll
            for (int q = 0; q < 4; q++)
                unpack_pair(vC[q], vD[3 - q], cmul(whC, Cq[q]), zz, pC + 256 * q);
        }
    }
    __syncthreads();

    // ---- mel projection: thread T does mels T and 127-T, both frames packed ----
    {
        const float df = 16000.0f / 1024.0f;
        #pragma unroll
        for (int h = 0; h < 2; h++) {
            int m = h ? (127 - T) : T;
            float f0 = fp[m];
            float f1 = fp[m + 1];
            float f2 = fp[m + 2];
            float inv_d0 = 1.0f / (f1 - f0);
            float inv_d1 = 1.0f / (f2 - f1);
            int klo = max(0, (int)(f0 / df));
            int khi = min(1024, (int)(f2 / df) + 1);
            ull acc = bc2(0.0f);
            float freq = (float)klo * df;
            for (int k = klo; k <= khi; k++) {
                float wgt = fminf((freq - f0) * inv_d0, (f2 - freq) * inv_d1);
                wgt = fmaxf(wgt, 0.0f);
                acc = fma2(pw_ld(zz, k), bc2(wgt), acc);
                freq += df;
            }
            float aA, aB;
            upk2(aA, aB, acc);
            g_mel[((size_t)bA * NFRM + tA) * NMELS + m] = aA;
            g_mel[((size_t)bB * NFRM + tB) * NMELS + m] = aB;
        }
    }
}

// ---------------- PCEN pass A: per-chunk partial IIR (m0 = 0) ----------------
__global__ __launch_bounds__(128) void pcen_partial_kernel() {
    const int b = blockIdx.x;
    const int c = blockIdx.y;
    const int m = threadIdx.x;
    const int t0 = c * CHLEN;
    const int len = min(CHLEN, NFRM - t0);

    const float* __restrict__ src = g_mel + ((size_t)b * NFRM + t0) * NMELS + m;
    float p = 0.0f;
    for (int k = 0; k < len; k++) {
        float x = src[(size_t)k * NMELS];
        p = fmaf(0.975f, p, 0.025f * x);
    }
    g_part[((size_t)b * NCHUNK + c) * NMELS + m] = p;
}

// ---------------- PCEN pass B: reconstruct state, emit outputs ----------------
__global__ __launch_bounds__(128) void pcen_out_kernel(float* __restrict__ out) {
    __shared__ float sm[NMELS * (CHLEN + 1)];

    const int b = blockIdx.x;
    const int c = blockIdx.y;
    const int m = threadIdx.x;
    const int t0 = c * CHLEN;
    const int len = min(CHLEN, NFRM - t0);

    float pow40 = 1.0f;
    #pragma unroll
    for (int i = 0; i < CHLEN; i++) pow40 *= 0.975f;

    const float* __restrict__ part = g_part + (size_t)b * NCHUNK * NMELS + m;
    float mst = 0.0f;
    for (int cp = 0; cp < c; cp++)
        mst = fmaf(mst, pow40, part[(size_t)cp * NMELS]);

    const float EPS = 1e-6f;
    const float ALPHA = 0.98f;
    const float DELTA = 2.0f;
    const float DELTA_R = 1.41421356237309515f;

    const float* __restrict__ src = g_mel + ((size_t)b * NFRM + t0) * NMELS + m;
    float* __restrict__ row = sm + (size_t)m * (CHLEN + 1);

    for (int k = 0; k < len; k++) {
        float x = src[(size_t)k * NMELS];
        mst = fmaf(0.975f, mst, 0.025f * x);
        float d = ex2_approx(-ALPHA * lg2_approx(EPS + mst));
        row[k] = sqrt_approx(fmaf(x, d, DELTA)) - DELTA_R;
    }
    __syncthreads();

    float* __restrict__ dst = out + (size_t)b * NMELS * NFRM + t0;
    const int total = NMELS * len;
    for (int j = m; j < total; j += NMELS) {
        int mr = j / len;
        int tt = j - mr * len;
        dst[(size_t)mr * NFRM + tt] = sm[(size_t)mr * (CHLEN + 1) + tt];
    }
}

extern "C" void kernel_launch(void* const* d_in, const int* in_sizes, int n_in,
                              void* d_out, int out_size) {
    const float* wave = (const float*)d_in[0];
    float* out = (float*)d_out;

    melspec_kernel<<<(BATCH * NFRM) / 2, 64>>>(wave);   // 10016 blocks, 1 frame-pair each

    dim3 pgrid(BATCH, NCHUNK);
    pcen_partial_kernel<<<pgrid, NMELS>>>();
    pcen_out_kernel<<<pgrid, NMELS>>>(out);
}

// round 14
// speedup vs baseline: 1.1066x; 1.1037x over previous
#include <cuda_runtime.h>
#include <math.h>

#define BATCH 64
#define WLEN  160000
#define NFRM  313          // 1 + 160000/512
#define HOP   512
#define NFFT  2048
#define MHALF 1024         // complex FFT length
#define NMELS 128
#define NPTS  130          // mel breakpoints

#define SK2(i) ((i) + ((i) >> 4))    // skew (slots are float4)
#define ZLEN4  1092

#define NCHUNK 16
#define CHLEN  20                    // 15*20 + 13 = 313

typedef unsigned long long ull;

__device__ float g_mel[BATCH * NFRM * NMELS];    // mel power, layout [b][t][m]
__device__ float g_part[BATCH * NCHUNK * NMELS]; // per-chunk partial IIR sums

// ---------------- packed f32x2 helpers ----------------
__device__ __forceinline__ ull pk2(float lo, float hi) {
    ull r; asm("mov.b64 %0, {%1, %2};" : "=l"(r) : "f"(lo), "f"(hi)); return r;
}
__device__ __forceinline__ ull bc2(float v) { return pk2(v, v); }
__device__ __forceinline__ void upk2(float& lo, float& hi, ull v) {
    asm("mov.b64 {%0, %1}, %2;" : "=f"(lo), "=f"(hi) : "l"(v));
}
__device__ __forceinline__ ull add2(ull a, ull b) {
    ull r; asm("add.rn.f32x2 %0, %1, %2;" : "=l"(r) : "l"(a), "l"(b)); return r;
}
__device__ __forceinline__ ull sub2(ull a, ull b) {
    ull r; asm("sub.rn.f32x2 %0, %1, %2;" : "=l"(r) : "l"(a), "l"(b)); return r;
}
__device__ __forceinline__ ull mul2(ull a, ull b) {
    ull r; asm("mul.rn.f32x2 %0, %1, %2;" : "=l"(r) : "l"(a), "l"(b)); return r;
}
__device__ __forceinline__ ull fma2(ull a, ull b, ull c) {
    ull r; asm("fma.rn.f32x2 %0, %1, %2, %3;" : "=l"(r) : "l"(a), "l"(b), "l"(c)); return r;
}

struct c2  { ull re, im; };                 // complex, 2 frames packed per component
struct tw2 { ull r, i, in; };               // packed twiddle

__device__ __forceinline__ float2 cmul(float2 a, float2 b) {
    return make_float2(a.x * b.x - a.y * b.y, a.x * b.y + a.y * b.x);
}
__device__ __forceinline__ tw2 mktw(float2 w) {
    tw2 t; t.r = bc2(w.x); t.i = bc2(w.y); t.in = bc2(-w.y); return t;
}
__device__ __forceinline__ c2 cmul2(c2 a, tw2 w) {
    c2 o;
    o.re = fma2(a.re, w.r, mul2(a.im, w.in));
    o.im = fma2(a.re, w.i, mul2(a.im, w.r));
    return o;
}
__device__ __forceinline__ void radix4p(c2& a0, c2& a1, c2& a2, c2& a3,
                                        tw2 w1, tw2 w2, tw2 w3) {
    c2 b1 = cmul2(a1, w1);
    c2 b2 = cmul2(a2, w2);
    c2 b3 = cmul2(a3, w3);
    ull t0r = add2(a0.re, b2.re), t0i = add2(a0.im, b2.im);
    ull t1r = sub2(a0.re, b2.re), t1i = sub2(a0.im, b2.im);
    ull t2r = add2(b1.re, b3.re), t2i = add2(b1.im, b3.im);
    ull t3r = sub2(b1.im, b3.im), t3i = sub2(b3.re, b1.re);   // -i*(b1-b3)
    a0.re = add2(t0r, t2r); a0.im = add2(t0i, t2i);
    a1.re = add2(t1r, t3r); a1.im = add2(t1i, t3i);
    a2.re = sub2(t0r, t2r); a2.im = sub2(t0i, t2i);
    a3.re = sub2(t1r, t3r); a3.im = sub2(t1i, t3i);
}
__device__ __forceinline__ void radix4p_nt(c2& a0, c2& a1, c2& a2, c2& a3) {
    ull t0r = add2(a0.re, a2.re), t0i = add2(a0.im, a2.im);
    ull t1r = sub2(a0.re, a2.re), t1i = sub2(a0.im, a2.im);
    ull t2r = add2(a1.re, a3.re), t2i = add2(a1.im, a3.im);
    ull t3r = sub2(a1.im, a3.im), t3i = sub2(a3.re, a1.re);
    a0.re = add2(t0r, t2r); a0.im = add2(t0i, t2i);
    a1.re = add2(t1r, t3r); a1.im = add2(t1i, t3i);
    a2.re = sub2(t0r, t2r); a2.im = sub2(t0i, t2i);
    a3.re = sub2(t1r, t3r); a3.im = sub2(t1i, t3i);
}
__device__ __forceinline__ c2 ld4(const float4* p) {
    float4 v = *p;
    c2 a; a.re = pk2(v.x, v.y); a.im = pk2(v.z, v.w); return a;
}
__device__ __forceinline__ void st4(float4* p, c2 a) {
    float4 v;
    upk2(v.x, v.y, a.re);
    upk2(v.z, v.w, a.im);
    *p = v;
}

__device__ __forceinline__ float sqrt_approx(float x) {
    float r; asm("sqrt.approx.f32 %0, %1;" : "=f"(r) : "f"(x)); return r;
}
__device__ __forceinline__ float lg2_approx(float x) {
    float r; asm("lg2.approx.f32 %0, %1;" : "=f"(r) : "f"(x)); return r;
}
__device__ __forceinline__ float ex2_approx(float x) {
    float r; asm("ex2.approx.f32 %0, %1;" : "=f"(r) : "f"(x)); return r;
}
__device__ __forceinline__ int reflect_idx(int j) {
    return (j < 0) ? -j : ((j >= WLEN) ? 2 * WLEN - 2 - j : j);
}

// real-FFT unpack for pair (k, 1024-k): a = z[k], cc = z[1024-k], w = exp(-i*pi*k/1024)
__device__ __forceinline__ void unpack_pair(c2 a, c2 cc, float2 w, ull* __restrict__ pw, int k) {
    ull EX = add2(a.re, cc.re);
    ull EY = sub2(a.im, cc.im);
    ull OX = add2(a.im, cc.im);
    ull OY = sub2(cc.re, a.re);
    ull wx = bc2(w.x), wy = bc2(w.y);
    ull RW = sub2(mul2(OX, wx), mul2(OY, wy));
    ull IW = fma2(OX, wy, mul2(OY, wx));
    ull Xr = add2(EX, RW), Xi = add2(EY, IW);
    ull Yr = sub2(EX, RW), Yi = sub2(IW, EY);
    const ull Q = bc2(0.25f);
    pw[k]        = mul2(fma2(Xi, Xi, mul2(Xr, Xr)), Q);
    pw[1024 - k] = mul2(fma2(Yi, Yi, mul2(Yr, Yr)), Q);
}

// stage-4 butterfly p (loads z[p+256q], applies twiddles, leaves outputs in v[q])
__device__ __forceinline__ void s4_bfly(const float4* __restrict__ zz, int p, float2 w, c2 v[4]) {
    const int o = SK2(p);   // SK2(p+256q) = SK2(p) + 272q  (p < 256)
    v[0] = ld4(&zz[o]);
    v[1] = ld4(&zz[o + 272]);
    v[2] = ld4(&zz[o + 544]);
    v[3] = ld4(&zz[o + 816]);
    float2 w2 = cmul(w, w);
    float2 w3 = cmul(w2, w);
    radix4p(v[0], v[1], v[2], v[3], mktw(w), mktw(w2), mktw(w3));
}

// ---------------- fused frame+window+FFT+power+mel, 2 frames SIMD-packed ----------------
// 64 threads per block; one frame PAIR per block; 16 complex points x 2 frames per thread.
__global__ __launch_bounds__(64, 8) void melspec_kernel(const float* __restrict__ wave) {
    __shared__ float4 zz[ZLEN4];       // (reA, reB, imA, imB)  17.5 KB
    __shared__ ull    pw[1056];        // (pwA, pwB) per bin     8.4 KB
    __shared__ float  fp[NPTS];

    const int T  = threadIdx.x;        // 0..63
    const int gA = blockIdx.x * 2;
    const int gB = gA + 1;
    const int bA = gA / NFRM, tA = gA - bA * NFRM;
    const int bB = gB / NFRM, tB = gB - bB * NFRM;

    const int skT = T + (T >> 4);      // SK2(T)

    // mel breakpoints
    for (int i = T; i < NPTS; i += 64) {
        const float mlo = 2595.0f * log10f(1.0f + 20.0f / 700.0f);
        const float mhi = 2595.0f * log10f(1.0f + 16000.0f / 700.0f);
        float m = mlo + (mhi - mlo) * (float)i / (float)(NPTS - 1);
        fp[i] = 700.0f * (exp10f(m / 2595.0f) - 1.0f);
    }

    // ---- staging: frames (reflect pad) * Hann; window rotor shared by both lanes ----
    const float* __restrict__ wbA = wave + (size_t)bA * WLEN;
    const float* __restrict__ wbB = wave + (size_t)bB * WLEN;
    const int p0A = tA * HOP - (NFFT / 2);
    const int p0B = tB * HOP - (NFFT / 2);
    const float CW = (float)M_PI / 1024.0f;
    float rs, rc;
    __sincosf(CW * (float)(2 * T), &rs, &rc);
    float2 rot = make_float2(rc, rs);
    // per-e step: dn = 64 complex = 128 real samples -> dtheta = CW*128 = pi/8
    const float2 RSTEP = make_float2(0.9238795325112867f, 0.3826834323650898f);   // exp(+i pi/8)
    const float CCW = 0.9999952938095760f;     // cos(pi/1024)
    const float SCW = 0.0030679567629659760f;  // sin(pi/1024)

    if (p0A >= 0 && p0B + NFFT <= WLEN && bA == bB) {
        const float2* __restrict__ wvA = (const float2*)(wbA + p0A) + T;
        const float2* __restrict__ wvB = (const float2*)(wbB + p0B) + T;
        #pragma unroll
        for (int e = 0; e < 16; e++) {
            float2 vA = wvA[64 * e];
            float2 vB = wvB[64 * e];
            float c1 = rot.x * CCW - rot.y * SCW;
            float w0 = 0.5f - 0.5f * rot.x;
            float w1 = 0.5f - 0.5f * c1;
            c2 z; z.re = pk2(vA.x * w0, vB.x * w0); z.im = pk2(vA.y * w1, vB.y * w1);
            st4(&zz[skT + 68 * e], z);
            rot = cmul(rot, RSTEP);
        }
    } else {
        #pragma unroll
        for (int e = 0; e < 16; e++) {
            int n = T + 64 * e;
            int jA = p0A + 2 * n, jB = p0B + 2 * n;
            float vAx = wbA[reflect_idx(jA)],     vBx = wbB[reflect_idx(jB)];
            float vAy = wbA[reflect_idx(jA + 1)], vBy = wbB[reflect_idx(jB + 1)];
            float c1 = rot.x * CCW - rot.y * SCW;
            float w0 = 0.5f - 0.5f * rot.x;
            float w1 = 0.5f - 0.5f * c1;
            c2 z; z.re = pk2(vAx * w0, vBx * w0); z.im = pk2(vAy * w1, vBy * w1);
            st4(&zz[skT + 68 * e], z);
            rot = cmul(rot, RSTEP);
        }
    }
    __syncthreads();

    // ---- merged stages 0+1: outputs [16T, 16T+16) ----
    {
        c2 y[4][4];   // y[j][p]
        #pragma unroll
        for (int j = 0; j < 4; j++) {
            unsigned old = (unsigned)(4 * T + j);
            unsigned rj = __brev(old) >> 24;
            rj = ((rj & 0x55u) << 1) | ((rj >> 1) & 0x55u);   // base-4 digit reverse
            int skrj = (int)rj + ((int)rj >> 4);
            c2 a0 = ld4(&zz[skrj]);
            c2 a1 = ld4(&zz[skrj + 272]);
            c2 a2 = ld4(&zz[skrj + 544]);
            c2 a3 = ld4(&zz[skrj + 816]);
            radix4p_nt(a0, a1, a2, a3);
            y[j][0] = a0; y[j][1] = a1; y[j][2] = a2; y[j][3] = a3;
        }
        __syncthreads();   // all gathers complete block-wide before any store

        const float2 W16_1[4] = { {1.f,0.f}, {0.92387953251f,-0.38268343236f},
                                  {0.70710678119f,-0.70710678119f}, {0.38268343236f,-0.92387953251f} };
        const float2 W16_2[4] = { {1.f,0.f}, {0.70710678119f,-0.70710678119f},
                                  {0.f,-1.f}, {-0.70710678119f,-0.70710678119f} };
        const float2 W16_3[4] = { {1.f,0.f}, {0.38268343236f,-0.92387953251f},
                                  {-0.70710678119f,-0.70710678119f}, {-0.92387953251f,0.38268343236f} };
        #pragma unroll
        for (int p = 0; p < 4; p++)
            radix4p(y[0][p], y[1][p], y[2][p], y[3][p],
                    mktw(W16_1[p]), mktw(W16_2[p]), mktw(W16_3[p]));

        const int st = 17 * T;   // SK2(16T + c) = 17T + c, c < 16
        #pragma unroll
        for (int q = 0; q < 4; q++)
            #pragma unroll
            for (int p = 0; p < 4; p++)
                st4(&zz[st + p + 4 * q], y[q][p]);
    }
    __syncthreads();

    // ---- merged stages 2+3: thread owns {256C + 16u + j0}, in place ----
    {
        const int C  = T >> 4;
        const int j0 = T & 15;
        const int base = 272 * C + j0;   // SK2(256C + j0); +17 per u
        c2 v[16];
        #pragma unroll
        for (int u = 0; u < 16; u++)
            v[u] = ld4(&zz[base + 17 * u]);

        // stage 2: twiddle exp(-2*pi*i*j0/64)
        {
            float s, c;
            __sincosf(-(float)M_PI * (float)j0 / 32.0f, &s, &c);
            float2 w1 = make_float2(c, s);
            float2 w2 = cmul(w1, w1);
            float2 w3 = cmul(w2, w1);
            tw2 t1 = mktw(w1), t2 = mktw(w2), t3 = mktw(w3);
            #pragma unroll
            for (int a = 0; a < 4; a++)
                radix4p(v[4*a+0], v[4*a+1], v[4*a+2], v[4*a+3], t1, t2, t3);
        }
        // stage 3: w1(bq) = exp(-2*pi*i*(16bq + j0)/256) via rotor (dn=16 -> dtheta=pi/8)
        {
            float s, c;
            __sincosf(-(float)M_PI * (float)j0 / 128.0f, &s, &c);
            float2 w = make_float2(c, s);
            const float2 STEP3 = make_float2(0.9238795325112867f, -0.3826834323650898f); // exp(-i pi/8)
            #pragma unroll
            for (int bq = 0; bq < 4; bq++) {
                float2 w2 = cmul(w, w);
                float2 w3 = cmul(w2, w);
                radix4p(v[bq], v[4+bq], v[8+bq], v[12+bq], mktw(w), mktw(w2), mktw(w3));
                w = cmul(w, STEP3);
            }
        }
        #pragma unroll
        for (int u = 0; u < 16; u++)
            st4(&zz[base + 17 * u], v[u]);
    }
    __syncthreads();

    // ---- stage 4 + real-FFT unpack fused in registers ----
    // thread T owns the pairing-closed butterfly set {T, 256-T, 127-T, 129+T}
    {
        // stage-4 twiddles: w(p) = exp(-2*pi*i*p/1024)
        float s4, c4;
        __sincosf(-(float)M_PI * (float)T / 512.0f, &s4, &c4);
        float2 wA = make_float2(c4, s4);                       // w(T)
        const float2 c1s = make_float2(0.9999811752826011f, -0.0061358846491544753f); // w(1)
        float2 wT1 = cmul(wA, c1s);                            // w(T+1)
        const float R2 = 0.70710678118654752f;
        const float2 K4 = make_float2(R2, -R2);                // exp(-i pi/4) = w(128) = wh(256)
        float2 wB = (T == 0) ? K4 : make_float2(-wA.y, -wA.x); // w(256-T); T=0 -> w(128)
        float2 wC = cmul(K4, make_float2(wT1.x, -wT1.y));      // w(127-T)
        float2 wD = cmul(K4, wT1);                             // w(129+T)

        // unpack half-twiddles: wh(p) = exp(-i*pi*p/1024)
        float hs, hc;
        __sincosf(-(float)M_PI * (float)T / 1024.0f, &hs, &hc);
        float2 whA = make_float2(hc, hs);                      // wh(T)
        const float2 ch1 = make_float2(0.9999952938095760f, -0.0030679567629659760f); // wh(1)
        float2 whT1 = cmul(whA, ch1);                          // wh(T+1)
        const float2 K8 = make_float2(0.92387953251128674f, -0.38268343236508977f);   // wh(128) = exp(-i pi/8)
        float2 whC = cmul(K8, make_float2(whT1.x, -whT1.y));   // wh(127-T)

        const float2 Cq[4] = { {1.f, 0.f}, {R2, -R2}, {0.f, -1.f}, {-R2, -R2} };  // wh(256q)

        const int pA = T;
        const int pB = (T == 0) ? 128 : 256 - T;
        const int pC = 127 - T;
        const int pD = 129 + T;

        // group 1: butterflies pA, pB
        {
            c2 vA[4], vB[4];
            s4_bfly(zz, pA, wA, vA);
            s4_bfly(zz, pB, wB, vB);
            if (T == 0) {
                ull x0 = add2(vA[0].re, vA[0].im);
                ull x1 = sub2(vA[0].re, vA[0].im);
                pw[0]    = mul2(x0, x0);
                pw[1024] = mul2(x1, x1);
                unpack_pair(vA[1], vA[3], K4,                     pw, 256);
                unpack_pair(vA[2], vA[2], make_float2(0.f, -1.f), pw, 512);
                unpack_pair(vB[0], vB[3], K8,                     pw, 128);
                unpack_pair(vB[1], vB[2], cmul(K8, Cq[1]),        pw, 384);
            } else {
                #pragma unroll
                for (int q = 0; q < 4; q++)
                    unpack_pair(vA[q], vB[3 - q], cmul(whA, Cq[q]), pw, pA + 256 * q);
            }
        }
        // group 2: butterflies pC, pD (uniform for all threads)
        {
            c2 vC[4], vD[4];
            s4_bfly(zz, pC, wC, vC);
            s4_bfly(zz, pD, wD, vD);
            #pragma unroll
            for (int q = 0; q < 4; q++)
                unpack_pair(vC[q], vD[3 - q], cmul(whC, Cq[q]), pw, pC + 256 * q);
        }
    }
    __syncthreads();

    // ---- mel projection: thread T does mels T and 127-T, both frames packed ----
    {
        const float df = 16000.0f / 1024.0f;
        #pragma unroll
        for (int h = 0; h < 2; h++) {
            int m = h ? (127 - T) : T;
            float f0 = fp[m];
            float f1 = fp[m + 1];
            float f2 = fp[m + 2];
            float inv_d0 = 1.0f / (f1 - f0);
            float inv_d1 = 1.0f / (f2 - f1);
            int klo = max(0, (int)(f0 / df));
            int khi = min(1024, (int)(f2 / df) + 1);
            ull acc = bc2(0.0f);
            float freq = (float)klo * df;
            for (int k = klo; k <= khi; k++) {
                float wgt = fminf((freq - f0) * inv_d0, (f2 - freq) * inv_d1);
                wgt = fmaxf(wgt, 0.0f);
                acc = fma2(pw[k], bc2(wgt), acc);
                freq += df;
            }
            float aA, aB;
            upk2(aA, aB, acc);
            g_mel[((size_t)bA * NFRM + tA) * NMELS + m] = aA;
            g_mel[((size_t)bB * NFRM + tB) * NMELS + m] = aB;
        }
    }
}

// ---------------- PCEN pass A: per-chunk partial IIR (m0 = 0) ----------------
__global__ __launch_bounds__(128) void pcen_partial_kernel() {
    const int b = blockIdx.x;
    const int c = blockIdx.y;
    const int m = threadIdx.x;
    const int t0 = c * CHLEN;
    const int len = min(CHLEN, NFRM - t0);

    const float* __restrict__ src = g_mel + ((size_t)b * NFRM + t0) * NMELS + m;
    float p = 0.0f;
    for (int k = 0; k < len; k++) {
        float x = src[(size_t)k * NMELS];
        p = fmaf(0.975f, p, 0.025f * x);
    }
    g_part[((size_t)b * NCHUNK + c) * NMELS + m] = p;
}

// ---------------- PCEN pass B: reconstruct state, emit outputs ----------------
__global__ __launch_bounds__(128) void pcen_out_kernel(float* __restrict__ out) {
    __shared__ float sm[NMELS * (CHLEN + 1)];

    const int b = blockIdx.x;
    const int c = blockIdx.y;
    const int m = threadIdx.x;
    const int t0 = c * CHLEN;
    const int len = min(CHLEN, NFRM - t0);

    // decay across one full chunk: 0.975^CHLEN (exact repeated multiply)
    float powC = 1.0f;
    #pragma unroll
    for (int i = 0; i < CHLEN; i++) powC *= 0.975f;

    const float* __restrict__ part = g_part + (size_t)b * NCHUNK * NMELS + m;
    float mst = 0.0f;
    for (int cp = 0; cp < c; cp++)
        mst = fmaf(mst, powC, part[(size_t)cp * NMELS]);

    const float EPS = 1e-6f;
    const float ALPHA = 0.98f;
    const float DELTA = 2.0f;
    const float DELTA_R = 1.41421356237309515f;

    const float* __restrict__ src = g_mel + ((size_t)b * NFRM + t0) * NMELS + m;
    float* __restrict__ row = sm + (size_t)m * (CHLEN + 1);

    for (int k = 0; k < len; k++) {
        float x = src[(size_t)k * NMELS];
        mst = fmaf(0.975f, mst, 0.025f * x);
        float d = ex2_approx(-ALPHA * lg2_approx(EPS + mst));
        row[k] = sqrt_approx(fmaf(x, d, DELTA)) - DELTA_R;
    }
    __syncthreads();

    float* __restrict__ dst = out + (size_t)b * NMELS * NFRM + t0;
    const int total = NMELS * len;
    for (int j = m; j < total; j += NMELS) {
        int mr = j / len;
        int tt = j - mr * len;
        dst[(size_t)mr * NFRM + tt] = sm[(size_t)mr * (CHLEN + 1) + tt];
    }
}

extern "C" void kernel_launch(void* const* d_in, const int* in_sizes, int n_in,
                              void* d_out, int out_size) {
    const float* wave = (const float*)d_in[0];
    float* out = (float*)d_out;

    melspec_kernel<<<(BATCH * NFRM) / 2, 64>>>(wave);   // 10016 blocks, 1 frame-pair each

    dim3 pgrid(BATCH, NCHUNK);
    pcen_partial_kernel<<<pgrid, NMELS>>>();
    pcen_out_kernel<<<pgrid, NMELS>>>(out);
}

// round 15
// speedup vs baseline: 1.1734x; 1.0603x over previous
#include <cuda_runtime.h>
#include <math.h>

#define BATCH 64
#define WLEN  160000
#define NFRM  313          // 1 + 160000/512
#define HOP   512
#define NFFT  2048
#define MHALF 1024         // complex FFT length
#define NMELS 128
#define NPTS  130          // mel breakpoints

// skew for float4 slots: f(p) = p + (p>>4) + (p>>8)
#define SKF(p) ((p) + ((p) >> 4) + ((p) >> 8))
#define ZLEN4  1092                  // max slot = SKF(1023)=1089

#define NCHUNK 16
#define CHLEN  20                    // 15*20 + 13 = 313

typedef unsigned long long ull;

__device__ float g_mel[BATCH * NFRM * NMELS];    // mel power, layout [b][t][m]
__device__ float g_part[BATCH * NCHUNK * NMELS]; // per-chunk partial IIR sums

// ---------------- packed f32x2 helpers ----------------
__device__ __forceinline__ ull pk2(float lo, float hi) {
    ull r; asm("mov.b64 %0, {%1, %2};" : "=l"(r) : "f"(lo), "f"(hi)); return r;
}
__device__ __forceinline__ ull bc2(float v) { return pk2(v, v); }
__device__ __forceinline__ void upk2(float& lo, float& hi, ull v) {
    asm("mov.b64 {%0, %1}, %2;" : "=f"(lo), "=f"(hi) : "l"(v));
}
__device__ __forceinline__ ull add2(ull a, ull b) {
    ull r; asm("add.rn.f32x2 %0, %1, %2;" : "=l"(r) : "l"(a), "l"(b)); return r;
}
__device__ __forceinline__ ull sub2(ull a, ull b) {
    ull r; asm("sub.rn.f32x2 %0, %1, %2;" : "=l"(r) : "l"(a), "l"(b)); return r;
}
__device__ __forceinline__ ull mul2(ull a, ull b) {
    ull r; asm("mul.rn.f32x2 %0, %1, %2;" : "=l"(r) : "l"(a), "l"(b)); return r;
}
__device__ __forceinline__ ull fma2(ull a, ull b, ull c) {
    ull r; asm("fma.rn.f32x2 %0, %1, %2, %3;" : "=l"(r) : "l"(a), "l"(b), "l"(c)); return r;
}

struct c2  { ull re, im; };                 // complex, 2 frames packed per component
struct tw2 { ull r, i, in; };               // packed twiddle

__device__ __forceinline__ float2 cmul(float2 a, float2 b) {
    return make_float2(a.x * b.x - a.y * b.y, a.x * b.y + a.y * b.x);
}
__device__ __forceinline__ tw2 mktw(float2 w) {
    tw2 t; t.r = bc2(w.x); t.i = bc2(w.y); t.in = bc2(-w.y); return t;
}
__device__ __forceinline__ c2 cmul2(c2 a, tw2 w) {
    c2 o;
    o.re = fma2(a.re, w.r, mul2(a.im, w.in));
    o.im = fma2(a.re, w.i, mul2(a.im, w.r));
    return o;
}

// DIF radix-4: butterfly FIRST, twiddles on outputs 1..3.
// y0 = t0+t2; y1 = (t1 - i t3)*w1; y2 = (t0-t2)*w2; y3 = (t1 + i t3)*w3
__device__ __forceinline__ void radix4p_dif(c2& a0, c2& a1, c2& a2, c2& a3,
                                            tw2 w1, tw2 w2, tw2 w3) {
    ull t0r = add2(a0.re, a2.re), t0i = add2(a0.im, a2.im);
    ull t1r = sub2(a0.re, a2.re), t1i = sub2(a0.im, a2.im);
    ull t2r = add2(a1.re, a3.re), t2i = add2(a1.im, a3.im);
    ull t3r = sub2(a1.re, a3.re), t3i = sub2(a1.im, a3.im);
    c2 y1p, y2p, y3p;
    y1p.re = add2(t1r, t3i);  y1p.im = sub2(t1i, t3r);   // t1 - i*t3
    y2p.re = sub2(t0r, t2r);  y2p.im = sub2(t0i, t2i);
    y3p.re = sub2(t1r, t3i);  y3p.im = add2(t1i, t3r);   // t1 + i*t3
    a0.re = add2(t0r, t2r);   a0.im = add2(t0i, t2i);
    a1 = cmul2(y1p, w1);
    a2 = cmul2(y2p, w2);
    a3 = cmul2(y3p, w3);
}
// twiddle-free DIF radix-4 (final stage)
__device__ __forceinline__ void radix4p_dif_nt(c2& a0, c2& a1, c2& a2, c2& a3) {
    ull t0r = add2(a0.re, a2.re), t0i = add2(a0.im, a2.im);
    ull t1r = sub2(a0.re, a2.re), t1i = sub2(a0.im, a2.im);
    ull t2r = add2(a1.re, a3.re), t2i = add2(a1.im, a3.im);
    ull t3r = sub2(a1.re, a3.re), t3i = sub2(a1.im, a3.im);
    a0.re = add2(t0r, t2r);  a0.im = add2(t0i, t2i);
    c2 y1, y2, y3;
    y1.re = add2(t1r, t3i);  y1.im = sub2(t1i, t3r);
    y2.re = sub2(t0r, t2r);  y2.im = sub2(t0i, t2i);
    y3.re = sub2(t1r, t3i);  y3.im = add2(t1i, t3r);
    a1 = y1; a2 = y2; a3 = y3;
}

__device__ __forceinline__ c2 ld4(const float4* p) {
    float4 v = *p;
    c2 a; a.re = pk2(v.x, v.y); a.im = pk2(v.z, v.w); return a;
}
__device__ __forceinline__ void st4(float4* p, c2 a) {
    float4 v;
    upk2(v.x, v.y, a.re);
    upk2(v.z, v.w, a.im);
    *p = v;
}

__device__ __forceinline__ float sqrt_approx(float x) {
    float r; asm("sqrt.approx.f32 %0, %1;" : "=f"(r) : "f"(x)); return r;
}
__device__ __forceinline__ float lg2_approx(float x) {
    float r; asm("lg2.approx.f32 %0, %1;" : "=f"(r) : "f"(x)); return r;
}
__device__ __forceinline__ float ex2_approx(float x) {
    float r; asm("ex2.approx.f32 %0, %1;" : "=f"(r) : "f"(x)); return r;
}
__device__ __forceinline__ int reflect_idx(int j) {
    return (j < 0) ? -j : ((j >= WLEN) ? 2 * WLEN - 2 - j : j);
}

// real-FFT unpack for pair (k, 1024-k): a = z[k], cc = z[1024-k], w = exp(-i*pi*k/1024)
__device__ __forceinline__ void unpack_pair(c2 a, c2 cc, float2 w, ull* __restrict__ pw, int k) {
    ull EX = add2(a.re, cc.re);
    ull EY = sub2(a.im, cc.im);
    ull OX = add2(a.im, cc.im);
    ull OY = sub2(cc.re, a.re);
    ull wx = bc2(w.x), wy = bc2(w.y);
    ull RW = sub2(mul2(OX, wx), mul2(OY, wy));
    ull IW = fma2(OX, wy, mul2(OY, wx));
    ull Xr = add2(EX, RW), Xi = add2(EY, IW);
    ull Yr = sub2(EX, RW), Yi = sub2(IW, EY);
    const ull Q = bc2(0.25f);
    pw[k]        = mul2(fma2(Xi, Xi, mul2(Xr, Xr)), Q);
    pw[1024 - k] = mul2(fma2(Yi, Yi, mul2(Yr, Yr)), Q);
}

// final DIF stage for output family r: butterfly g = rev'(r) at positions {4g+j}
// (twiddle-free) yields v[q] = X[r + 256q].
__device__ __forceinline__ void dif4_final(const float4* __restrict__ zz, int r, c2 v[4]) {
    const int g = ((r & 3) << 6) | (((r >> 2) & 3) << 4) | (((r >> 4) & 3) << 2) | ((r >> 6) & 3);
    const int base = 4 * g + (g >> 2) + (g >> 6);   // SKF(4g+j) = base + j
    v[0] = ld4(&zz[base]);
    v[1] = ld4(&zz[base + 1]);
    v[2] = ld4(&zz[base + 2]);
    v[3] = ld4(&zz[base + 3]);
    radix4p_dif_nt(v[0], v[1], v[2], v[3]);
}

// ---------------- fused frame+window+FFT+power+mel, 2 frames SIMD-packed, DIF ----------------
// 64 threads per block; one frame PAIR per block; 16 complex points x 2 frames per thread.
__global__ __launch_bounds__(64, 8) void melspec_kernel(const float* __restrict__ wave) {
    __shared__ float4 zz[ZLEN4];       // (reA, reB, imA, imB)  17.5 KB
    __shared__ ull    pw[1056];        // (pwA, pwB) per bin     8.4 KB
    __shared__ float  fp[NPTS];

    const int T  = threadIdx.x;        // 0..63
    const int gA = blockIdx.x * 2;
    const int gB = gA + 1;
    const int bA = gA / NFRM, tA = gA - bA * NFRM;
    const int bB = gB / NFRM, tB = gB - bB * NFRM;

    const int skT = T + (T >> 4);      // SKF(T), T < 256

    // mel breakpoints
    for (int i = T; i < NPTS; i += 64) {
        const float mlo = 2595.0f * log10f(1.0f + 20.0f / 700.0f);
        const float mhi = 2595.0f * log10f(1.0f + 16000.0f / 700.0f);
        float m = mlo + (mhi - mlo) * (float)i / (float)(NPTS - 1);
        fp[i] = 700.0f * (exp10f(m / 2595.0f) - 1.0f);
    }

    // W16[u] = exp(-2*pi*i*u/16)
    const float2 W16c[4] = { {1.f, 0.f},
                             {0.92387953251128674f, -0.38268343236508977f},
                             {0.70710678118654752f, -0.70710678118654752f},
                             {0.38268343236508977f, -0.92387953251128674f} };

    // ---- load frames (reflect pad) * Hann into registers: x[e] = z[T+64e] ----
    const float* __restrict__ wbA = wave + (size_t)bA * WLEN;
    const float* __restrict__ wbB = wave + (size_t)bB * WLEN;
    const int p0A = tA * HOP - (NFFT / 2);
    const int p0B = tB * HOP - (NFFT / 2);
    const float CW = (float)M_PI / 1024.0f;
    c2 x[16];
    {
        // window rotor: theta(n) = pi*n/512 (n complex idx); per-e step dn=64 -> dtheta=pi/8
        float rs, rc;
        __sincosf(CW * (float)(2 * T), &rs, &rc);
        float2 rot = make_float2(rc, rs);
        const float2 RSTEP = make_float2(0.9238795325112867f, 0.3826834323650898f);   // exp(+i pi/8)
        const float CCW = 0.9999952938095760f;     // cos(pi/1024)
        const float SCW = 0.0030679567629659760f;  // sin(pi/1024)

        if (p0A >= 0 && p0B + NFFT <= WLEN && bA == bB) {
            const float2* __restrict__ wvA = (const float2*)(wbA + p0A) + T;
            const float2* __restrict__ wvB = (const float2*)(wbB + p0B) + T;
            #pragma unroll
            for (int e = 0; e < 16; e++) {
                float2 vA = wvA[64 * e];
                float2 vB = wvB[64 * e];
                float c1 = rot.x * CCW - rot.y * SCW;
                float w0 = 0.5f - 0.5f * rot.x;
                float w1 = 0.5f - 0.5f * c1;
                x[e].re = pk2(vA.x * w0, vB.x * w0);
                x[e].im = pk2(vA.y * w1, vB.y * w1);
                rot = cmul(rot, RSTEP);
            }
        } else {
            #pragma unroll
            for (int e = 0; e < 16; e++) {
                int n = T + 64 * e;
                int jA = p0A + 2 * n, jB = p0B + 2 * n;
                float vAx = wbA[reflect_idx(jA)],     vBx = wbB[reflect_idx(jB)];
                float vAy = wbA[reflect_idx(jA + 1)], vBy = wbB[reflect_idx(jB + 1)];
                float c1 = rot.x * CCW - rot.y * SCW;
                float w0 = 0.5f - 0.5f * rot.x;
                float w1 = 0.5f - 0.5f * c1;
                x[e].re = pk2(vAx * w0, vBx * w0);
                x[e].im = pk2(vAy * w1, vBy * w1);
                rot = cmul(rot, RSTEP);
            }
        }
    }

    // ---- DIF stage 0 (in registers): butterfly over q for each u; e = u + 4q ----
    // twiddle w_u = W_1024^(T+64u) = W_1024^T * W16[u]
    {
        float s, c;
        __sincosf(-(float)M_PI * (float)T / 512.0f, &s, &c);   // W_1024^T = exp(-2pi i T/1024)
        float2 wT = make_float2(c, s);
        #pragma unroll
        for (int u = 0; u < 4; u++) {
            float2 w1 = cmul(wT, W16c[u]);
            float2 w2 = cmul(w1, w1);
            float2 w3 = cmul(w2, w1);
            radix4p_dif(x[u], x[u + 4], x[u + 8], x[u + 12],
                        mktw(w1), mktw(w2), mktw(w3));
        }
    }
    // ---- DIF stage 1 (in registers): butterfly over u for each subproblem q' ----
    // twiddle W_256^(T*q'') -- same for all q'
    {
        float s, c;
        __sincosf(-(float)M_PI * (float)T / 128.0f, &s, &c);   // W_256^T = exp(-2pi i T/256)
        float2 w1 = make_float2(c, s);
        float2 w2 = cmul(w1, w1);
        float2 w3 = cmul(w2, w1);
        tw2 t1 = mktw(w1), t2 = mktw(w2), t3 = mktw(w3);
        #pragma unroll
        for (int qp = 0; qp < 4; qp++)
            radix4p_dif(x[4 * qp], x[4 * qp + 1], x[4 * qp + 2], x[4 * qp + 3], t1, t2, t3);
        // store x[4q' + q''] at p = 256q' + 64q'' + T -> slot skT + 68q'' + 273q'
        #pragma unroll
        for (int qp = 0; qp < 4; qp++)
            #pragma unroll
            for (int qpp = 0; qpp < 4; qpp++)
                st4(&zz[skT + 68 * qpp + 273 * qp], x[4 * qp + qpp]);
    }
    __syncthreads();

    // ---- DIF stages 2+3 (merged in registers): thread owns p = 64C + 16u + 4v + b0 ----
    {
        const int C  = T >> 2;
        const int b0 = T & 3;
        // SKF(64C + 16u + 4v + b0) = 68C + (C>>2) + 17u + 4v + b0
        const int base = 68 * C + (C >> 2) + b0;
        c2 v2[4][4];   // v2[u][v]
        #pragma unroll
        for (int u = 0; u < 4; u++)
            #pragma unroll
            for (int v = 0; v < 4; v++)
                v2[u][v] = ld4(&zz[base + 17 * u + 4 * v]);

        // stage 2: butterfly over u for each v; twiddle W_64^((4v+b0)*q)
        // rotor: w(v) = exp(-2pi i (4v+b0)/64); per-v step dn=4 -> W_64^4 = exp(-i pi/8)
        {
            float s, c;
            __sincosf(-(float)M_PI * (float)b0 / 32.0f, &s, &c);   // W_64^b0
            float2 w = make_float2(c, s);
            const float2 STEP = make_float2(0.9238795325112867f, -0.3826834323650898f); // exp(-i pi/8)
            #pragma unroll
            for (int v = 0; v < 4; v++) {
                float2 w2 = cmul(w, w);
                float2 w3 = cmul(w2, w);
                radix4p_dif(v2[0][v], v2[1][v], v2[2][v], v2[3][v],
                            mktw(w), mktw(w2), mktw(w3));
                w = cmul(w, STEP);
            }
        }
        // stage 3: butterfly over v for each u'; twiddle W_16^(b0*q) = W16c[b0]^q
        {
            float2 w1 = W16c[b0];
            float2 w2 = cmul(w1, w1);
            float2 w3 = cmul(w2, w1);
            tw2 t1 = mktw(w1), t2 = mktw(w2), t3 = mktw(w3);
            #pragma unroll
            for (int u = 0; u < 4; u++)
                radix4p_dif(v2[u][0], v2[u][1], v2[u][2], v2[u][3], t1, t2, t3);
        }
        #pragma unroll
        for (int u = 0; u < 4; u++)
            #pragma unroll
            for (int v = 0; v < 4; v++)
                st4(&zz[base + 17 * u + 4 * v], v2[u][v]);
    }
    __syncthreads();

    // ---- DIF final stage + real-FFT unpack fused in registers ----
    // thread T owns output families r in {T, 256-T, 127-T, 129+T} (T=0: {0,128,127,129});
    // family r gives X[r + 256q], pairing with family 256-r exactly as before.
    {
        // unpack half-twiddles: wh(r) = exp(-i*pi*r/1024)
        float hs, hc;
        __sincosf(-(float)M_PI * (float)T / 1024.0f, &hs, &hc);
        float2 whA = make_float2(hc, hs);                      // wh(T)
        const float2 ch1 = make_float2(0.9999952938095760f, -0.0030679567629659760f); // wh(1)
        float2 whT1 = cmul(whA, ch1);                          // wh(T+1)
        const float R2 = 0.70710678118654752f;
        const float2 K4 = make_float2(R2, -R2);                // wh(256) = exp(-i pi/4)
        const float2 K8 = make_float2(0.92387953251128674f, -0.38268343236508977f);   // wh(128) = exp(-i pi/8)
        float2 whC = cmul(K8, make_float2(whT1.x, -whT1.y));   // wh(127-T)

        const float2 Cq[4] = { {1.f, 0.f}, {R2, -R2}, {0.f, -1.f}, {-R2, -R2} };  // wh(256q)

        const int rA = T;
        const int rB = (T == 0) ? 128 : 256 - T;
        const int rC = 127 - T;
        const int rD = 129 + T;

        // group 1: families rA, rB
        {
            c2 vA[4], vB[4];
            dif4_final(zz, rA, vA);
            dif4_final(zz, rB, vB);
            if (T == 0) {
                ull x0 = add2(vA[0].re, vA[0].im);
                ull x1 = sub2(vA[0].re, vA[0].im);
                pw[0]    = mul2(x0, x0);
                pw[1024] = mul2(x1, x1);
                unpack_pair(vA[1], vA[3], K4,                     pw, 256);
                unpack_pair(vA[2], vA[2], make_float2(0.f, -1.f), pw, 512);
                unpack_pair(vB[0], vB[3], K8,                     pw, 128);
                unpack_pair(vB[1], vB[2], cmul(K8, Cq[1]),        pw, 384);
            } else {
                #pragma unroll
                for (int q = 0; q < 4; q++)
                    unpack_pair(vA[q], vB[3 - q], cmul(whA, Cq[q]), pw, rA + 256 * q);
            }
        }
        // group 2: families rC, rD (uniform for all threads)
        {
            c2 vC[4], vD[4];
            dif4_final(zz, rC, vC);
            dif4_final(zz, rD, vD);
            #pragma unroll
            for (int q = 0; q < 4; q++)
                unpack_pair(vC[q], vD[3 - q], cmul(whC, Cq[q]), pw, rC + 256 * q);
        }
    }
    __syncthreads();

    // ---- mel projection: thread T does mels T and 127-T, both frames packed ----
    {
        const float df = 16000.0f / 1024.0f;
        #pragma unroll
        for (int h = 0; h < 2; h++) {
            int m = h ? (127 - T) : T;
            float f0 = fp[m];
            float f1 = fp[m + 1];
            float f2 = fp[m + 2];
            float inv_d0 = 1.0f / (f1 - f0);
            float inv_d1 = 1.0f / (f2 - f1);
            int klo = max(0, (int)(f0 / df));
            int khi = min(1024, (int)(f2 / df) + 1);
            ull acc = bc2(0.0f);
            float freq = (float)klo * df;
            for (int k = klo; k <= khi; k++) {
                float wgt = fminf((freq - f0) * inv_d0, (f2 - freq) * inv_d1);
                wgt = fmaxf(wgt, 0.0f);
                acc = fma2(pw[k], bc2(wgt), acc);
                freq += df;
            }
            float aA, aB;
            upk2(aA, aB, acc);
            g_mel[((size_t)bA * NFRM + tA) * NMELS + m] = aA;
            g_mel[((size_t)bB * NFRM + tB) * NMELS + m] = aB;
        }
    }
}

// ---------------- PCEN pass A: per-chunk partial IIR (m0 = 0) ----------------
__global__ __launch_bounds__(128) void pcen_partial_kernel() {
    const int b = blockIdx.x;
    const int c = blockIdx.y;
    const int m = threadIdx.x;
    const int t0 = c * CHLEN;
    const int len = min(CHLEN, NFRM - t0);

    const float* __restrict__ src = g_mel + ((size_t)b * NFRM + t0) * NMELS + m;
    float p = 0.0f;
    for (int k = 0; k < len; k++) {
        float x = src[(size_t)k * NMELS];
        p = fmaf(0.975f, p, 0.025f * x);
    }
    g_part[((size_t)b * NCHUNK + c) * NMELS + m] = p;
}

// ---------------- PCEN pass B: reconstruct state, emit outputs ----------------
__global__ __launch_bounds__(128) void pcen_out_kernel(float* __restrict__ out) {
    __shared__ float sm[NMELS * (CHLEN + 1)];

    const int b = blockIdx.x;
    const int c = blockIdx.y;
    const int m = threadIdx.x;
    const int t0 = c * CHLEN;
    const int len = min(CHLEN, NFRM - t0);

    float powC = 1.0f;
    #pragma unroll
    for (int i = 0; i < CHLEN; i++) powC *= 0.975f;

    const float* __restrict__ part = g_part + (size_t)b * NCHUNK * NMELS + m;
    float mst = 0.0f;
    for (int cp = 0; cp < c; cp++)
        mst = fmaf(mst, powC, part[(size_t)cp * NMELS]);

    const float EPS = 1e-6f;
    const float ALPHA = 0.98f;
    const float DELTA = 2.0f;
    const float DELTA_R = 1.41421356237309515f;

    const float* __restrict__ src = g_mel + ((size_t)b * NFRM + t0) * NMELS + m;
    float* __restrict__ row = sm + (size_t)m * (CHLEN + 1);

    for (int k = 0; k < len; k++) {
        float x = src[(size_t)k * NMELS];
        mst = fmaf(0.975f, mst, 0.025f * x);
        float d = ex2_approx(-ALPHA * lg2_approx(EPS + mst));
        row[k] = sqrt_approx(fmaf(x, d, DELTA)) - DELTA_R;
    }
    __syncthreads();

    float* __restrict__ dst = out + (size_t)b * NMELS * NFRM + t0;
    const int total = NMELS * len;
    for (int j = m; j < total; j += NMELS) {
        int mr = j / len;
        int tt = j - mr * len;
        dst[(size_t)mr * NFRM + tt] = sm[(size_t)mr * (CHLEN + 1) + tt];
    }
}

extern "C" void kernel_launch(void* const* d_in, const int* in_sizes, int n_in,
                              void* d_out, int out_size) {
    const float* wave = (const float*)d_in[0];
    float* out = (float*)d_out;

    melspec_kernel<<<(BATCH * NFRM) / 2, 64>>>(wave);   // 10016 blocks, 1 frame-pair each

    dim3 pgrid(BATCH, NCHUNK);
    pcen_partial_kernel<<<pgrid, NMELS>>>();
    pcen_out_kernel<<<pgrid, NMELS>>>(out);
}

// round 16
// speedup vs baseline: 1.1919x; 1.0158x over previous
#include <cuda_runtime.h>
#include <math.h>

#define BATCH 64
#define WLEN  160000
#define NFRM  313          // 1 + 160000/512
#define HOP   512
#define NFFT  2048
#define MHALF 1024         // complex FFT length
#define NMELS 128
#define NPTS  130          // mel breakpoints

// skew for float4 slots: f(p) = p + (p>>4) + (p>>8)
#define SKF(p) ((p) + ((p) >> 4) + ((p) >> 8))
#define ZLEN4  1092                  // max slot = SKF(1023)=1089

#define NCHUNK 16
#define CHLEN  20                    // 15*20 + 13 = 313

typedef unsigned long long ull;

__device__ float g_mel[BATCH * NFRM * NMELS];    // mel power, layout [b][t][m]
__device__ float g_part[BATCH * NCHUNK * NMELS]; // per-chunk partial IIR sums

// ---------------- packed f32x2 helpers ----------------
__device__ __forceinline__ ull pk2(float lo, float hi) {
    ull r; asm("mov.b64 %0, {%1, %2};" : "=l"(r) : "f"(lo), "f"(hi)); return r;
}
__device__ __forceinline__ ull bc2(float v) { return pk2(v, v); }
__device__ __forceinline__ void upk2(float& lo, float& hi, ull v) {
    asm("mov.b64 {%0, %1}, %2;" : "=f"(lo), "=f"(hi) : "l"(v));
}
__device__ __forceinline__ ull add2(ull a, ull b) {
    ull r; asm("add.rn.f32x2 %0, %1, %2;" : "=l"(r) : "l"(a), "l"(b)); return r;
}
__device__ __forceinline__ ull sub2(ull a, ull b) {
    ull r; asm("sub.rn.f32x2 %0, %1, %2;" : "=l"(r) : "l"(a), "l"(b)); return r;
}
__device__ __forceinline__ ull mul2(ull a, ull b) {
    ull r; asm("mul.rn.f32x2 %0, %1, %2;" : "=l"(r) : "l"(a), "l"(b)); return r;
}
__device__ __forceinline__ ull fma2(ull a, ull b, ull c) {
    ull r; asm("fma.rn.f32x2 %0, %1, %2, %3;" : "=l"(r) : "l"(a), "l"(b), "l"(c)); return r;
}

struct c2  { ull re, im; };                 // complex, 2 frames packed per component
struct tw2 { ull r, i, in; };               // packed twiddle

__device__ __forceinline__ float2 cmul(float2 a, float2 b) {
    return make_float2(a.x * b.x - a.y * b.y, a.x * b.y + a.y * b.x);
}
__device__ __forceinline__ tw2 mktw(float2 w) {
    tw2 t; t.r = bc2(w.x); t.i = bc2(w.y); t.in = bc2(-w.y); return t;
}
__device__ __forceinline__ c2 cmul2(c2 a, tw2 w) {
    c2 o;
    o.re = fma2(a.re, w.r, mul2(a.im, w.in));
    o.im = fma2(a.re, w.i, mul2(a.im, w.r));
    return o;
}

// DIF radix-4: butterfly FIRST, twiddles on outputs 1..3.
__device__ __forceinline__ void radix4p_dif(c2& a0, c2& a1, c2& a2, c2& a3,
                                            tw2 w1, tw2 w2, tw2 w3) {
    ull t0r = add2(a0.re, a2.re), t0i = add2(a0.im, a2.im);
    ull t1r = sub2(a0.re, a2.re), t1i = sub2(a0.im, a2.im);
    ull t2r = add2(a1.re, a3.re), t2i = add2(a1.im, a3.im);
    ull t3r = sub2(a1.re, a3.re), t3i = sub2(a1.im, a3.im);
    c2 y1p, y2p, y3p;
    y1p.re = add2(t1r, t3i);  y1p.im = sub2(t1i, t3r);   // t1 - i*t3
    y2p.re = sub2(t0r, t2r);  y2p.im = sub2(t0i, t2i);
    y3p.re = sub2(t1r, t3i);  y3p.im = add2(t1i, t3r);   // t1 + i*t3
    a0.re = add2(t0r, t2r);   a0.im = add2(t0i, t2i);
    a1 = cmul2(y1p, w1);
    a2 = cmul2(y2p, w2);
    a3 = cmul2(y3p, w3);
}
// twiddle-free DIF radix-4 (final stage)
__device__ __forceinline__ void radix4p_dif_nt(c2& a0, c2& a1, c2& a2, c2& a3) {
    ull t0r = add2(a0.re, a2.re), t0i = add2(a0.im, a2.im);
    ull t1r = sub2(a0.re, a2.re), t1i = sub2(a0.im, a2.im);
    ull t2r = add2(a1.re, a3.re), t2i = add2(a1.im, a3.im);
    ull t3r = sub2(a1.re, a3.re), t3i = sub2(a1.im, a3.im);
    a0.re = add2(t0r, t2r);  a0.im = add2(t0i, t2i);
    c2 y1, y2, y3;
    y1.re = add2(t1r, t3i);  y1.im = sub2(t1i, t3r);
    y2.re = sub2(t0r, t2r);  y2.im = sub2(t0i, t2i);
    y3.re = sub2(t1r, t3i);  y3.im = add2(t1i, t3r);
    a1 = y1; a2 = y2; a3 = y3;
}

__device__ __forceinline__ c2 ld4(const float4* p) {
    float4 v = *p;
    c2 a; a.re = pk2(v.x, v.y); a.im = pk2(v.z, v.w); return a;
}
__device__ __forceinline__ void st4(float4* p, c2 a) {
    float4 v;
    upk2(v.x, v.y, a.re);
    upk2(v.z, v.w, a.im);
    *p = v;
}

__device__ __forceinline__ float sqrt_approx(float x) {
    float r; asm("sqrt.approx.f32 %0, %1;" : "=f"(r) : "f"(x)); return r;
}
__device__ __forceinline__ float lg2_approx(float x) {
    float r; asm("lg2.approx.f32 %0, %1;" : "=f"(r) : "f"(x)); return r;
}
__device__ __forceinline__ float ex2_approx(float x) {
    float r; asm("ex2.approx.f32 %0, %1;" : "=f"(r) : "f"(x)); return r;
}
__device__ __forceinline__ int reflect_idx(int j) {
    return (j < 0) ? -j : ((j >= WLEN) ? 2 * WLEN - 2 - j : j);
}

// real-FFT unpack for pair (k, 1024-k): a = z[k], cc = z[1024-k], w = exp(-i*pi*k/1024)
__device__ __forceinline__ void unpack_pair(c2 a, c2 cc, float2 w, ull* __restrict__ pw, int k) {
    ull EX = add2(a.re, cc.re);
    ull EY = sub2(a.im, cc.im);
    ull OX = add2(a.im, cc.im);
    ull OY = sub2(cc.re, a.re);
    ull wx = bc2(w.x), wy = bc2(w.y);
    ull RW = sub2(mul2(OX, wx), mul2(OY, wy));
    ull IW = fma2(OX, wy, mul2(OY, wx));
    ull Xr = add2(EX, RW), Xi = add2(EY, IW);
    ull Yr = sub2(EX, RW), Yi = sub2(IW, EY);
    const ull Q = bc2(0.25f);
    pw[k]        = mul2(fma2(Xi, Xi, mul2(Xr, Xr)), Q);
    pw[1024 - k] = mul2(fma2(Yi, Yi, mul2(Yr, Yr)), Q);
}

// final DIF stage for output family r: butterfly g = rev'(r) at positions {4g+j}
// (twiddle-free) yields v[q] = X[r + 256q].
__device__ __forceinline__ void dif4_final(const float4* __restrict__ zz, int r, c2 v[4]) {
    const int g = ((r & 3) << 6) | (((r >> 2) & 3) << 4) | (((r >> 4) & 3) << 2) | ((r >> 6) & 3);
    const int base = 4 * g + (g >> 2) + (g >> 6);   // SKF(4g+j) = base + j
    v[0] = ld4(&zz[base]);
    v[1] = ld4(&zz[base + 1]);
    v[2] = ld4(&zz[base + 2]);
    v[3] = ld4(&zz[base + 3]);
    radix4p_dif_nt(v[0], v[1], v[2], v[3]);
}

// ---------------- fused frame+window+FFT+power+mel, 2 frames SIMD-packed, DIF ----------------
// 64 threads per block; one frame PAIR per block; 16 complex points x 2 frames per thread.
__global__ __launch_bounds__(64, 8) void melspec_kernel(const float* __restrict__ wave) {
    __shared__ float4 zz[ZLEN4];       // (reA, reB, imA, imB)  17.5 KB
    __shared__ ull    pw[1056];        // (pwA, pwB) per bin     8.4 KB
    __shared__ float  fp[NPTS];

    const int T  = threadIdx.x;        // 0..63
    const int gA = blockIdx.x * 2;
    const int gB = gA + 1;
    const int bA = gA / NFRM, tA = gA - bA * NFRM;
    const int bB = gB / NFRM, tB = gB - bB * NFRM;

    const int skT = T + (T >> 4);      // SKF(T), T < 256

    // mel breakpoints
    for (int i = T; i < NPTS; i += 64) {
        const float mlo = 2595.0f * log10f(1.0f + 20.0f / 700.0f);
        const float mhi = 2595.0f * log10f(1.0f + 16000.0f / 700.0f);
        float m = mlo + (mhi - mlo) * (float)i / (float)(NPTS - 1);
        fp[i] = 700.0f * (exp10f(m / 2595.0f) - 1.0f);
    }

    // W16[u] = exp(-2*pi*i*u/16)
    const float2 W16c[4] = { {1.f, 0.f},
                             {0.92387953251128674f, -0.38268343236508977f},
                             {0.70710678118654752f, -0.70710678118654752f},
                             {0.38268343236508977f, -0.92387953251128674f} };

    // ---- load frames (reflect pad) * Hann into registers: x[e] = z[T+64e] ----
    const float* __restrict__ wbA = wave + (size_t)bA * WLEN;
    const float* __restrict__ wbB = wave + (size_t)bB * WLEN;
    const int p0A = tA * HOP - (NFFT / 2);
    const int p0B = tB * HOP - (NFFT / 2);
    const float CW = (float)M_PI / 1024.0f;
    c2 x[16];
    {
        // window rotor: theta(n) = pi*n/512 (n complex idx); per-e step dn=64 -> dtheta=pi/8
        float rs, rc;
        __sincosf(CW * (float)(2 * T), &rs, &rc);
        float2 rot = make_float2(rc, rs);
        const float2 RSTEP = make_float2(0.9238795325112867f, 0.3826834323650898f);   // exp(+i pi/8)
        const float CCW = 0.9999952938095760f;     // cos(pi/1024)
        const float SCW = 0.0030679567629659760f;  // sin(pi/1024)

        if (p0A >= 0 && p0B + NFFT <= WLEN && bA == bB) {
            const float2* __restrict__ wvA = (const float2*)(wbA + p0A) + T;
            const float2* __restrict__ wvB = (const float2*)(wbB + p0B) + T;
            #pragma unroll
            for (int e = 0; e < 16; e++) {
                float2 vA = wvA[64 * e];
                float2 vB = wvB[64 * e];
                float c1 = rot.x * CCW - rot.y * SCW;
                float w0 = 0.5f - 0.5f * rot.x;
                float w1 = 0.5f - 0.5f * c1;
                x[e].re = pk2(vA.x * w0, vB.x * w0);
                x[e].im = pk2(vA.y * w1, vB.y * w1);
                rot = cmul(rot, RSTEP);
            }
        } else {
            #pragma unroll
            for (int e = 0; e < 16; e++) {
                int n = T + 64 * e;
                int jA = p0A + 2 * n, jB = p0B + 2 * n;
                float vAx = wbA[reflect_idx(jA)],     vBx = wbB[reflect_idx(jB)];
                float vAy = wbA[reflect_idx(jA + 1)], vBy = wbB[reflect_idx(jB + 1)];
                float c1 = rot.x * CCW - rot.y * SCW;
                float w0 = 0.5f - 0.5f * rot.x;
                float w1 = 0.5f - 0.5f * c1;
                x[e].re = pk2(vAx * w0, vBx * w0);
                x[e].im = pk2(vAy * w1, vBy * w1);
                rot = cmul(rot, RSTEP);
            }
        }
    }

    // ---- DIF stage 0 (in registers): butterfly over q for each u; e = u + 4q ----
    {
        float s, c;
        __sincosf(-(float)M_PI * (float)T / 512.0f, &s, &c);   // W_1024^T
        float2 wT = make_float2(c, s);
        #pragma unroll
        for (int u = 0; u < 4; u++) {
            float2 w1 = cmul(wT, W16c[u]);
            float2 w2 = cmul(w1, w1);
            float2 w3 = cmul(w2, w1);
            radix4p_dif(x[u], x[u + 4], x[u + 8], x[u + 12],
                        mktw(w1), mktw(w2), mktw(w3));
        }
    }
    // ---- DIF stage 1 (in registers) ----
    {
        float s, c;
        __sincosf(-(float)M_PI * (float)T / 128.0f, &s, &c);   // W_256^T
        float2 w1 = make_float2(c, s);
        float2 w2 = cmul(w1, w1);
        float2 w3 = cmul(w2, w1);
        tw2 t1 = mktw(w1), t2 = mktw(w2), t3 = mktw(w3);
        #pragma unroll
        for (int qp = 0; qp < 4; qp++)
            radix4p_dif(x[4 * qp], x[4 * qp + 1], x[4 * qp + 2], x[4 * qp + 3], t1, t2, t3);
        // store x[4q' + q''] at p = 256q' + 64q'' + T -> slot skT + 68q'' + 273q'
        #pragma unroll
        for (int qp = 0; qp < 4; qp++)
            #pragma unroll
            for (int qpp = 0; qpp < 4; qpp++)
                st4(&zz[skT + 68 * qpp + 273 * qp], x[4 * qp + qpp]);
    }
    __syncthreads();

    // ---- DIF stages 2+3 (merged in registers): thread owns p = 64C + 16u + 4v + b0 ----
    {
        const int C  = T >> 2;
        const int b0 = T & 3;
        const int base = 68 * C + (C >> 2) + b0;   // SKF(64C + b0)
        c2 v2[4][4];   // v2[u][v]
        #pragma unroll
        for (int u = 0; u < 4; u++)
            #pragma unroll
            for (int v = 0; v < 4; v++)
                v2[u][v] = ld4(&zz[base + 17 * u + 4 * v]);

        // stage 2: twiddle W_64^(4v+b0); per-v step dn=4 -> W_64^4 = exp(-i pi/8)
        {
            float s, c;
            __sincosf(-(float)M_PI * (float)b0 / 32.0f, &s, &c);   // W_64^b0
            float2 w = make_float2(c, s);
            const float2 STEP = make_float2(0.9238795325112867f, -0.3826834323650898f); // exp(-i pi/8)
            #pragma unroll
            for (int v = 0; v < 4; v++) {
                float2 w2 = cmul(w, w);
                float2 w3 = cmul(w2, w);
                radix4p_dif(v2[0][v], v2[1][v], v2[2][v], v2[3][v],
                            mktw(w), mktw(w2), mktw(w3));
                w = cmul(w, STEP);
            }
        }
        // stage 3: twiddle W_16^b0 = W16c[b0]
        {
            float2 w1 = W16c[b0];
            float2 w2 = cmul(w1, w1);
            float2 w3 = cmul(w2, w1);
            tw2 t1 = mktw(w1), t2 = mktw(w2), t3 = mktw(w3);
            #pragma unroll
            for (int u = 0; u < 4; u++)
                radix4p_dif(v2[u][0], v2[u][1], v2[u][2], v2[u][3], t1, t2, t3);
        }
        #pragma unroll
        for (int u = 0; u < 4; u++)
            #pragma unroll
            for (int v = 0; v < 4; v++)
                st4(&zz[base + 17 * u + 4 * v], v2[u][v]);
    }
    __syncthreads();

    // ---- DIF final stage + real-FFT unpack fused in registers ----
    // thread T owns output families r in {T, 256-T, 127-T, 129+T} (T=0: {0,128,127,129}).
    {
        float hs, hc;
        __sincosf(-(float)M_PI * (float)T / 1024.0f, &hs, &hc);
        float2 whA = make_float2(hc, hs);                      // wh(T)
        const float2 ch1 = make_float2(0.9999952938095760f, -0.0030679567629659760f); // wh(1)
        float2 whT1 = cmul(whA, ch1);                          // wh(T+1)
        const float R2 = 0.70710678118654752f;
        const float2 K4 = make_float2(R2, -R2);                // wh(256)
        const float2 K8 = make_float2(0.92387953251128674f, -0.38268343236508977f);   // wh(128)
        float2 whC = cmul(K8, make_float2(whT1.x, -whT1.y));   // wh(127-T)

        const float2 Cq[4] = { {1.f, 0.f}, {R2, -R2}, {0.f, -1.f}, {-R2, -R2} };  // wh(256q)

        const int rA = T;
        const int rB = (T == 0) ? 128 : 256 - T;
        const int rC = 127 - T;
        const int rD = 129 + T;

        // group 1: families rA, rB
        {
            c2 vA[4], vB[4];
            dif4_final(zz, rA, vA);
            dif4_final(zz, rB, vB);
            if (T == 0) {
                ull x0 = add2(vA[0].re, vA[0].im);
                ull x1 = sub2(vA[0].re, vA[0].im);
                pw[0]    = mul2(x0, x0);
                pw[1024] = mul2(x1, x1);
                unpack_pair(vA[1], vA[3], K4,                     pw, 256);
                unpack_pair(vA[2], vA[2], make_float2(0.f, -1.f), pw, 512);
                unpack_pair(vB[0], vB[3], K8,                     pw, 128);
                unpack_pair(vB[1], vB[2], cmul(K8, Cq[1]),        pw, 384);
            } else {
                #pragma unroll
                for (int q = 0; q < 4; q++)
                    unpack_pair(vA[q], vB[3 - q], cmul(whA, Cq[q]), pw, rA + 256 * q);
            }
        }
        // group 2: families rC, rD (uniform for all threads)
        {
            c2 vC[4], vD[4];
            dif4_final(zz, rC, vC);
            dif4_final(zz, rD, vD);
            #pragma unroll
            for (int q = 0; q < 4; q++)
                unpack_pair(vC[q], vD[3 - q], cmul(whC, Cq[q]), pw, rC + 256 * q);
        }
    }
    __syncthreads();

    // ---- mel projection: piecewise-linear weight via packed slope recurrence ----
    // weight(k) = min((k*df-f0)*inv_d0, (f2-k*df)*inv_d1), clamped bins excluded by
    // bounds klo=ceil(f0/df), khi=floor(f2/df); apex split at kmid=floor(f1/df)
    // (up-slope is the min for freq<=f1; kmid >= klo-1 always, so the down loop
    // never ingests pre-f0 bins).
    {
        const float df = 16000.0f / 1024.0f;
        const float inv_df = 1024.0f / 16000.0f;
        #pragma unroll
        for (int h = 0; h < 2; h++) {
            int m = h ? (127 - T) : T;
            float f0 = fp[m];
            float f1 = fp[m + 1];
            float f2 = fp[m + 2];
            float inv_d0 = 1.0f / (f1 - f0);
            float inv_d1 = 1.0f / (f2 - f1);
            int klo  = (int)ceilf(f0 * inv_df);
            int kmid = (int)(f1 * inv_df);
            int khi  = min(1024, (int)(f2 * inv_df));

            ull acc = bc2(0.0f);
            // up-slope: w = (k*df - f0)*inv_d0, dw = df*inv_d0
            ull wp  = bc2(((float)klo * df - f0) * inv_d0);
            ull dwp = bc2(df * inv_d0);
            for (int k = klo; k <= kmid; k++) {
                acc = fma2(pw[k], wp, acc);
                wp = add2(wp, dwp);
            }
            // down-slope: w = (f2 - k*df)*inv_d1, dw = -df*inv_d1
            ull wq  = bc2((f2 - (float)(kmid + 1) * df) * inv_d1);
            ull dwq = bc2(df * inv_d1);
            for (int k = kmid + 1; k <= khi; k++) {
                acc = fma2(pw[k], wq, acc);
                wq = sub2(wq, dwq);
            }

            float aA, aB;
            upk2(aA, aB, acc);
            g_mel[((size_t)bA * NFRM + tA) * NMELS + m] = aA;
            g_mel[((size_t)bB * NFRM + tB) * NMELS + m] = aB;
        }
    }
}

// ---------------- PCEN pass A: per-chunk partial IIR (m0 = 0) ----------------
__global__ __launch_bounds__(128) void pcen_partial_kernel() {
    const int b = blockIdx.x;
    const int c = blockIdx.y;
    const int m = threadIdx.x;
    const int t0 = c * CHLEN;
    const int len = min(CHLEN, NFRM - t0);

    const float* __restrict__ src = g_mel + ((size_t)b * NFRM + t0) * NMELS + m;
    float p = 0.0f;
    for (int k = 0; k < len; k++) {
        float x = src[(size_t)k * NMELS];
        p = fmaf(0.975f, p, 0.025f * x);
    }
    g_part[((size_t)b * NCHUNK + c) * NMELS + m] = p;
}

// ---------------- PCEN pass B: reconstruct state, emit outputs ----------------
__global__ __launch_bounds__(128) void pcen_out_kernel(float* __restrict__ out) {
    __shared__ float sm[NMELS * (CHLEN + 1)];

    const int b = blockIdx.x;
    const int c = blockIdx.y;
    const int m = threadIdx.x;
    const int t0 = c * CHLEN;
    const int len = min(CHLEN, NFRM - t0);

    float powC = 1.0f;
    #pragma unroll
    for (int i = 0; i < CHLEN; i++) powC *= 0.975f;

    const float* __restrict__ part = g_part + (size_t)b * NCHUNK * NMELS + m;
    float mst = 0.0f;
    for (int cp = 0; cp < c; cp++)
        mst = fmaf(mst, powC, part[(size_t)cp * NMELS]);

    const float EPS = 1e-6f;
    const float ALPHA = 0.98f;
    const float DELTA = 2.0f;
    const float DELTA_R = 1.41421356237309515f;

    const float* __restrict__ src = g_mel + ((size_t)b * NFRM + t0) * NMELS + m;
    float* __restrict__ row = sm + (size_t)m * (CHLEN + 1);

    for (int k = 0; k < len; k++) {
        float x = src[(size_t)k * NMELS];
        mst = fmaf(0.975f, mst, 0.025f * x);
        float d = ex2_approx(-ALPHA * lg2_approx(EPS + mst));
        row[k] = sqrt_approx(fmaf(x, d, DELTA)) - DELTA_R;
    }
    __syncthreads();

    float* __restrict__ dst = out + (size_t)b * NMELS * NFRM + t0;
    const int total = NMELS * len;
    for (int j = m; j < total; j += NMELS) {
        int mr = j / len;
        int tt = j - mr * len;
        dst[(size_t)mr * NFRM + tt] = sm[(size_t)mr * (CHLEN + 1) + tt];
    }
}

extern "C" void kernel_launch(void* const* d_in, const int* in_sizes, int n_in,
                              void* d_out, int out_size) {
    const float* wave = (const float*)d_in[0];
    float* out = (float*)d_out;

    melspec_kernel<<<(BATCH * NFRM) / 2, 64>>>(wave);   // 10016 blocks, 1 frame-pair each

    dim3 pgrid(BATCH, NCHUNK);
    pcen_partial_kernel<<<pgrid, NMELS>>>();
    pcen_out_kernel<<<pgrid, NMELS>>>(out);
}